// round 2
// baseline (speedup 1.0000x reference)
#include <cuda_runtime.h>
#include <math.h>

#define BATCH 8
#define UPC   256
#define HH    256
#define WWD   256
#define HWN   65536
#define MTOT  (BATCH*HWN)   // 524288

// ---------------- scratch (static device globals; allocation-free) ----------------
__device__ float g_xu[(size_t)BATCH*UPC*HWN];    // upsampled x, NCHW (537 MB)
__device__ float g_f [(size_t)MTOT*256];         // concat(xc, y), NHWC (537 MB)
__device__ float g_h1[(size_t)MTOT*128];         // mlp1 out / identity
__device__ float g_ln[(size_t)MTOT*128];         // layernorm out
__device__ float g_t1[(size_t)MTOT*64];
__device__ float g_t2[(size_t)MTOT*64];
__device__ float g_t3[(size_t)MTOT*128];
__device__ float g_w9[9*256*128];                // conv weights as [off][ci][co]
__device__ float g_bias1[BATCH*128];
__device__ float g_bias3[BATCH*64];
__device__ float g_bias4[BATCH*64];
__device__ float g_part[BATCH*512*2];
__device__ float g_stats[BATCH*2];               // mu, rsigma per batch

// ---------------- prep: conv weight transpose + s-folded biases ----------------
__global__ void prep_w9(const float* __restrict__ cw){
    int i = blockIdx.x*256 + threadIdx.x;
    if (i < 9*256*128){
        int co  = i & 127;
        int ci  = (i >> 7) & 255;
        int off = i >> 15;
        g_w9[i] = cw[(co*256 + ci)*9 + off];
    }
}

__global__ void prep_bias(const float* __restrict__ s,
                          const float* __restrict__ m1w, const float* __restrict__ m1b,
                          const float* __restrict__ w3,  const float* __restrict__ b3,
                          const float* __restrict__ w4,  const float* __restrict__ b4){
    int t = threadIdx.x;
    for (int b = 0; b < BATCH; b++){
        float sb = s[b];
        if (t < 128) g_bias1[b*128+t] = m1b[t] + sb*m1w[256*128 + t];
        if (t < 64){
            g_bias3[b*64+t] = b3[t] + sb*w3[128*64 + t];
            g_bias4[b*64+t] = b4[t] + sb*w4[128*64 + t];
        }
    }
}

// ---------------- separable bicubic 2x upsample ----------------
__global__ void upsample_kernel(const float* __restrict__ x){
    int idx = blockIdx.x*256 + threadIdx.x;     // 2048 planes * 128 * 128
    int kw = idx & 127;
    int kh = (idx >> 7) & 127;
    int pl = idx >> 14;
    const float* xp = x + (size_t)pl*16384;
    float* op = g_xu + (size_t)pl*65536;

    int rr[5], cc[5];
    #pragma unroll
    for (int i = 0; i < 5; i++){
        int r = kh - 2 + i; rr[i] = min(max(r,0),127);
        int c = kw - 2 + i; cc[i] = min(max(c,0),127);
    }
    const float we0=-0.03515625f, we1=0.26171875f, we2=0.87890625f, we3=-0.10546875f;
    const float wo0=-0.10546875f, wo1=0.87890625f, wo2=0.26171875f, wo3=-0.03515625f;

    float he[5], ho[5];
    #pragma unroll
    for (int i = 0; i < 5; i++){
        const float* row = xp + rr[i]*128;
        float v0=row[cc[0]], v1=row[cc[1]], v2=row[cc[2]], v3=row[cc[3]], v4=row[cc[4]];
        he[i] = we0*v0 + we1*v1 + we2*v2 + we3*v3;
        ho[i] = wo0*v1 + wo1*v2 + wo2*v3 + wo3*v4;
    }
    float o00 = we0*he[0]+we1*he[1]+we2*he[2]+we3*he[3];
    float o01 = we0*ho[0]+we1*ho[1]+we2*ho[2]+we3*ho[3];
    float o10 = wo0*he[1]+wo1*he[2]+wo2*he[3]+wo3*he[4];
    float o11 = wo0*ho[1]+wo1*ho[2]+wo2*ho[3]+wo3*ho[4];

    *(float2*)(op + (2*kh  )*256 + 2*kw) = make_float2(o00, o01);
    *(float2*)(op + (2*kh+1)*256 + 2*kw) = make_float2(o10, o11);
}

// ---------------- y NCHW -> f NHWC (channels 128..255) ----------------
__global__ void ycopy_kernel(const float* __restrict__ y){
    __shared__ float tile[32][33];
    int w0 = blockIdx.x*32, c0 = blockIdx.y*32;
    int bh = blockIdx.z;
    int b = bh >> 8, h = bh & 255;
    int tx = threadIdx.x, ty = threadIdx.y;
    #pragma unroll
    for (int k = 0; k < 4; k++){
        int c = c0 + ty + k*8;
        tile[ty + k*8][tx] = y[(((size_t)b*128 + c)*256 + h)*256 + w0 + tx];
    }
    __syncthreads();
    #pragma unroll
    for (int k = 0; k < 4; k++){
        int w = w0 + ty + k*8;
        g_f[(((size_t)b*256 + h)*256 + w)*256 + 128 + c0 + tx] = tile[tx][ty + k*8];
    }
}

// ---------------- conv 3x3 as 9-offset implicit GEMM, 128x128 tile ----------------
__global__ __launch_bounds__(256) void conv_kernel(const float* __restrict__ convb){
    __shared__ float As[32][128];
    __shared__ float Bs[32][128];
    int bx = blockIdx.x;
    int w0 = (bx & 1)*128;
    int h  = (bx >> 1) & 255;
    int b  = bx >> 9;
    int tid = threadIdx.x;
    int tx = tid & 15, ty = tid >> 4;
    int posL = tid & 127;
    int kkL  = tid >> 7;     // 0/1
    int kkB  = tid >> 5;     // 0..7
    int nqB  = tid & 31;

    float acc[8][8];
    #pragma unroll
    for (int i = 0; i < 8; i++)
        #pragma unroll
        for (int j = 0; j < 8; j++) acc[i][j] = 0.f;

    for (int off = 0; off < 9; off++){
        int dh = off/3 - 1, dw = off%3 - 1;
        int hh = h + dh;
        if (hh < 0 || hh >= HH) continue;
        int wpos = w0 + posL + dw;
        bool wok = (wpos >= 0) && (wpos < WWD);
        const float* abase = g_xu + (size_t)b*UPC*HWN + (size_t)hh*WWD + wpos;
        const float* wbase = g_w9 + off*32768;

        for (int k0 = 0; k0 < 256; k0 += 32){
            #pragma unroll
            for (int p = 0; p < 16; p++){
                int kk = kkL + p*2;
                As[kk][posL] = wok ? abase[(size_t)(k0+kk)*HWN] : 0.f;
            }
            #pragma unroll
            for (int p = 0; p < 4; p++){
                int kk = kkB + p*8;
                *(float4*)&Bs[kk][nqB*4] = *(const float4*)&wbase[(k0+kk)*128 + nqB*4];
            }
            __syncthreads();
            #pragma unroll
            for (int kk = 0; kk < 32; kk++){
                float a[8], bb[8];
                *(float4*)&a[0]  = *(float4*)&As[kk][ty*8];
                *(float4*)&a[4]  = *(float4*)&As[kk][ty*8+4];
                *(float4*)&bb[0] = *(float4*)&Bs[kk][tx*8];
                *(float4*)&bb[4] = *(float4*)&Bs[kk][tx*8+4];
                #pragma unroll
                for (int i = 0; i < 8; i++)
                    #pragma unroll
                    for (int j = 0; j < 8; j++)
                        acc[i][j] = fmaf(a[i], bb[j], acc[i][j]);
            }
            __syncthreads();
        }
    }
    float bias[8];
    #pragma unroll
    for (int j = 0; j < 8; j++) bias[j] = convb[tx*8 + j];
    #pragma unroll
    for (int i = 0; i < 8; i++){
        int w = w0 + ty*8 + i;
        float* dst = g_f + (((size_t)b*HH + h)*WWD + w)*256 + tx*8;
        *(float4*)dst     = make_float4(acc[i][0]+bias[0], acc[i][1]+bias[1],
                                        acc[i][2]+bias[2], acc[i][3]+bias[3]);
        *(float4*)(dst+4) = make_float4(acc[i][4]+bias[4], acc[i][5]+bias[5],
                                        acc[i][6]+bias[6], acc[i][7]+bias[7]);
    }
}

// ---------------- generic tiled SGEMM (M-tile 128, K%32==0, N in {64,128}) ----------------
// EPI: 0 per-batch bias            1 shared bias
//      2 shared bias + relu        3 shared bias + relu + identity + NCHW scatter
//      4 per-batch bias + relu
template<int K, int N, int EPI>
__global__ __launch_bounds__(256) void gemm_kernel(
    const float* __restrict__ A, const float* __restrict__ Wt,
    const float* __restrict__ bias, float* __restrict__ out,
    const float* __restrict__ identity)
{
    constexpr int TN  = N/16;
    constexpr int NB4 = N/4;
    constexpr int KKP = 256/NB4;
    __shared__ float As[32][128];
    __shared__ float Bs[32][N];

    int m0  = blockIdx.x*128;
    int tid = threadIdx.x;
    int tx = tid & 15, ty = tid >> 4;
    int rowA = tid >> 3, kqA = tid & 7;
    int kkB = tid / NB4, nqB = tid % NB4;

    float acc[8][TN];
    #pragma unroll
    for (int i = 0; i < 8; i++)
        #pragma unroll
        for (int j = 0; j < TN; j++) acc[i][j] = 0.f;

    for (int k0 = 0; k0 < K; k0 += 32){
        #pragma unroll
        for (int p = 0; p < 4; p++){
            int r = rowA + p*32;
            float4 v = *(const float4*)&A[(size_t)(m0+r)*K + k0 + kqA*4];
            int kr = kqA*4;
            As[kr+0][r ^ (((kr+0)&7)<<2)] = v.x;
            As[kr+1][r ^ (((kr+1)&7)<<2)] = v.y;
            As[kr+2][r ^ (((kr+2)&7)<<2)] = v.z;
            As[kr+3][r ^ (((kr+3)&7)<<2)] = v.w;
        }
        #pragma unroll
        for (int p = 0; p < 32/KKP; p++){
            int kk = kkB + p*KKP;
            *(float4*)&Bs[kk][nqB*4] = *(const float4*)&Wt[(size_t)(k0+kk)*N + nqB*4];
        }
        __syncthreads();
        #pragma unroll
        for (int kk = 0; kk < 32; kk++){
            int sw = (kk & 7) << 2;
            float a[8], bb[TN];
            *(float4*)&a[0] = *(float4*)&As[kk][(ty*8  ) ^ sw];
            *(float4*)&a[4] = *(float4*)&As[kk][(ty*8+4) ^ sw];
            if constexpr (TN == 8){
                *(float4*)&bb[0] = *(float4*)&Bs[kk][tx*8];
                *(float4*)&bb[4] = *(float4*)&Bs[kk][tx*8+4];
            } else {
                *(float4*)&bb[0] = *(float4*)&Bs[kk][tx*4];
            }
            #pragma unroll
            for (int i = 0; i < 8; i++)
                #pragma unroll
                for (int j = 0; j < TN; j++)
                    acc[i][j] = fmaf(a[i], bb[j], acc[i][j]);
        }
        __syncthreads();
    }

    int b = m0 >> 16;
    const float* bp = (EPI == 0 || EPI == 4) ? (bias + b*N) : bias;
    float bv[TN];
    #pragma unroll
    for (int j = 0; j < TN; j++) bv[j] = bp[tx*TN + j];

    #pragma unroll
    for (int i = 0; i < 8; i++){
        int m = m0 + ty*8 + i;
        if constexpr (EPI == 3){
            int hw = m & 65535;
            #pragma unroll
            for (int j = 0; j < TN; j++){
                int n = tx*TN + j;
                float v = fmaxf(acc[i][j] + bv[j], 0.f)
                        + identity[(size_t)m*128 + n];
                out[((size_t)(b*128 + n))*65536 + hw] = v;
            }
        } else {
            float* dst = out + (size_t)m*N + tx*TN;
            #pragma unroll
            for (int j = 0; j < TN; j += 4){
                float4 v;
                v.x = acc[i][j+0] + bv[j+0];
                v.y = acc[i][j+1] + bv[j+1];
                v.z = acc[i][j+2] + bv[j+2];
                v.w = acc[i][j+3] + bv[j+3];
                if (EPI == 2 || EPI == 4){
                    v.x = fmaxf(v.x,0.f); v.y = fmaxf(v.y,0.f);
                    v.z = fmaxf(v.z,0.f); v.w = fmaxf(v.w,0.f);
                }
                *(float4*)&dst[j] = v;
            }
        }
    }
}

// ---------------- deterministic layernorm (per-batch scalar mu/var) ----------------
__global__ void ln_part(){
    int b = blockIdx.y, blk = blockIdx.x, tid = threadIdx.x;
    const float4* p = (const float4*)(g_h1 + (size_t)b*8388608 + (size_t)blk*16384);
    float s = 0.f, s2 = 0.f;
    for (int i = tid; i < 4096; i += 256){
        float4 v = p[i];
        s  += v.x + v.y + v.z + v.w;
        s2 += v.x*v.x + v.y*v.y + v.z*v.z + v.w*v.w;
    }
    __shared__ float sh[256], sh2[256];
    sh[tid] = s; sh2[tid] = s2; __syncthreads();
    for (int st = 128; st > 0; st >>= 1){
        if (tid < st){ sh[tid] += sh[tid+st]; sh2[tid] += sh2[tid+st]; }
        __syncthreads();
    }
    if (tid == 0){
        g_part[(b*512 + blk)*2    ] = sh[0];
        g_part[(b*512 + blk)*2 + 1] = sh2[0];
    }
}

__global__ void ln_finish(){
    int b = blockIdx.x, tid = threadIdx.x;
    float s = 0.f, s2 = 0.f;
    for (int i = tid; i < 512; i += 256){
        s  += g_part[(b*512 + i)*2];
        s2 += g_part[(b*512 + i)*2 + 1];
    }
    __shared__ float sh[256], sh2[256];
    sh[tid] = s; sh2[tid] = s2; __syncthreads();
    for (int st = 128; st > 0; st >>= 1){
        if (tid < st){ sh[tid] += sh[tid+st]; sh2[tid] += sh2[tid+st]; }
        __syncthreads();
    }
    if (tid == 0){
        const float invN = 1.f / 8388608.f;
        float mu  = sh[0] * invN;
        float var = sh2[0] * invN - mu*mu;
        g_stats[b*2]     = mu;
        g_stats[b*2 + 1] = rsqrtf(var + 1e-5f);
    }
}

__global__ void ln_apply(const float* __restrict__ lnw, const float* __restrict__ lnb){
    size_t e = ((size_t)blockIdx.x*256 + threadIdx.x)*4;
    int b = (int)(e >> 23);
    float mu = g_stats[b*2], rs = g_stats[b*2 + 1];
    size_t li = e & 8388607u;
    float4 h = *(const float4*)&g_h1[e];
    float4 w = *(const float4*)&lnw[li];
    float4 c = *(const float4*)&lnb[li];
    float4 o;
    o.x = (h.x - mu)*rs*w.x + c.x;
    o.y = (h.y - mu)*rs*w.y + c.y;
    o.z = (h.z - mu)*rs*w.z + c.z;
    o.w = (h.w - mu)*rs*w.w + c.w;
    *(float4*)&g_ln[e] = o;
}

// ---------------- launch ----------------
extern "C" void kernel_launch(void* const* d_in, const int* in_sizes, int n_in,
                              void* d_out, int out_size){
    const float* x      = (const float*)d_in[0];
    const float* y      = (const float*)d_in[1];
    const float* s      = (const float*)d_in[2];
    const float* conv_w = (const float*)d_in[4];
    const float* conv_b = (const float*)d_in[5];
    const float* mlp1_w = (const float*)d_in[6];
    const float* mlp1_b = (const float*)d_in[7];
    const float* ln_w   = (const float*)d_in[8];
    const float* ln_b   = (const float*)d_in[9];
    const float* m3_w1  = (const float*)d_in[10];
    const float* m3_b1  = (const float*)d_in[11];
    const float* m3_w2  = (const float*)d_in[12];
    const float* m3_b2  = (const float*)d_in[13];
    const float* m3_w3  = (const float*)d_in[14];
    const float* m3_b3  = (const float*)d_in[15];
    const float* m4_w1  = (const float*)d_in[16];
    const float* m4_b1  = (const float*)d_in[17];
    const float* m4_w2  = (const float*)d_in[18];
    const float* m4_b2  = (const float*)d_in[19];
    const float* m4_w3  = (const float*)d_in[20];
    const float* m4_b3  = (const float*)d_in[21];
    float* out = (float*)d_out;

    void *pf, *ph1, *pln, *pt1, *pt2, *pt3, *pb1, *pb3, *pb4;
    cudaGetSymbolAddress(&pf,  g_f);
    cudaGetSymbolAddress(&ph1, g_h1);
    cudaGetSymbolAddress(&pln, g_ln);
    cudaGetSymbolAddress(&pt1, g_t1);
    cudaGetSymbolAddress(&pt2, g_t2);
    cudaGetSymbolAddress(&pt3, g_t3);
    cudaGetSymbolAddress(&pb1, g_bias1);
    cudaGetSymbolAddress(&pb3, g_bias3);
    cudaGetSymbolAddress(&pb4, g_bias4);

    prep_w9<<<1152, 256>>>(conv_w);
    prep_bias<<<1, 256>>>(s, mlp1_w, mlp1_b, m3_w1, m3_b1, m4_w1, m4_b1);
    upsample_kernel<<<131072, 256>>>(x);
    ycopy_kernel<<<dim3(8, 4, 2048), dim3(32, 8)>>>(y);
    conv_kernel<<<4096, 256>>>(conv_b);

    // mlp1: f(K=256) -> h1(N=128), per-batch bias + relu
    gemm_kernel<256,128,4><<<4096, 256>>>((const float*)pf, mlp1_w,
                                          (const float*)pb1, (float*)ph1, nullptr);
    // layernorm
    ln_part<<<dim3(512, 8), 256>>>();
    ln_finish<<<8, 256>>>();
    ln_apply<<<65536, 256>>>(ln_w, ln_b);

    // mlp3
    gemm_kernel<128,64,0><<<4096, 256>>>((const float*)pln, m3_w1,
                                         (const float*)pb3, (float*)pt1, nullptr);
    gemm_kernel<64,64,1><<<4096, 256>>>((const float*)pt1, m3_w2,
                                        m3_b2, (float*)pt2, nullptr);
    gemm_kernel<64,128,2><<<4096, 256>>>((const float*)pt2, m3_w3,
                                         m3_b3, (float*)pt3, nullptr);
    // mlp4 (+ identity add + NCHW scatter)
    gemm_kernel<128,64,0><<<4096, 256>>>((const float*)pt3, m4_w1,
                                         (const float*)pb4, (float*)pt1, nullptr);
    gemm_kernel<64,64,1><<<4096, 256>>>((const float*)pt1, m4_w2,
                                        m4_b2, (float*)pt2, nullptr);
    gemm_kernel<64,128,3><<<4096, 256>>>((const float*)pt2, m4_w3,
                                         m4_b3, out, (const float*)ph1);
}

// round 4
// speedup vs baseline: 1.2459x; 1.2459x over previous
#include <cuda_runtime.h>
#include <math.h>
#include <stdint.h>

#define BATCH 8
#define UPC   256
#define HH    256
#define WWD   256
#define HWN   65536
#define MTOT  (BATCH*HWN)   // 524288

// ---------------- scratch (static device globals; allocation-free) ----------------
__device__ float g_xu [(size_t)BATCH*UPC*HWN];   // upsampled x, NCHW
__device__ float g_xuT[(size_t)BATCH*HWN*UPC];   // upsampled x, NHWC, tf32-rounded
__device__ float g_f [(size_t)MTOT*256];         // concat(xc, y), NHWC
__device__ float g_h1[(size_t)MTOT*128];
__device__ float g_ln[(size_t)MTOT*128];
__device__ float g_t1[(size_t)MTOT*64];
__device__ float g_t2[(size_t)MTOT*64];
__device__ float g_t3[(size_t)MTOT*128];
__device__ float g_w9t[9*128*256];               // conv weights [off][co][ci], tf32-rounded
__device__ float g_bias1[BATCH*128];
__device__ float g_bias3[BATCH*64];
__device__ float g_bias4[BATCH*64];
__device__ float g_part[BATCH*512*2];
__device__ float g_stats[BATCH*2];

__device__ __forceinline__ float to_tf32(float x){
    float r; asm("cvt.rna.tf32.f32 %0, %1;" : "=f"(r) : "f"(x)); return r;
}

__device__ __forceinline__ void mma_tf32(float c[4],
        uint32_t a0, uint32_t a1, uint32_t a2, uint32_t a3,
        uint32_t b0, uint32_t b1){
    asm volatile(
        "mma.sync.aligned.m16n8k8.row.col.f32.tf32.tf32.f32 "
        "{%0,%1,%2,%3}, {%4,%5,%6,%7}, {%8,%9}, {%0,%1,%2,%3};"
        : "+f"(c[0]), "+f"(c[1]), "+f"(c[2]), "+f"(c[3])
        : "r"(a0), "r"(a1), "r"(a2), "r"(a3), "r"(b0), "r"(b1));
}

// ---------------- prep: conv weight repack (tf32) + s-folded biases ----------------
__global__ void prep_w9t(const float* __restrict__ cw){
    int i = blockIdx.x*256 + threadIdx.x;   // 9*128*256 = 294912
    if (i < 9*128*256){
        int ci  = i & 255;
        int co  = (i >> 8) & 127;
        int off = i >> 15;
        g_w9t[i] = to_tf32(cw[(co*256 + ci)*9 + off]);
    }
}

__global__ void prep_bias(const float* __restrict__ s,
                          const float* __restrict__ m1w, const float* __restrict__ m1b,
                          const float* __restrict__ w3,  const float* __restrict__ b3,
                          const float* __restrict__ w4,  const float* __restrict__ b4){
    int t = threadIdx.x;
    for (int b = 0; b < BATCH; b++){
        float sb = s[b];
        if (t < 128) g_bias1[b*128+t] = m1b[t] + sb*m1w[256*128 + t];
        if (t < 64){
            g_bias3[b*64+t] = b3[t] + sb*w3[128*64 + t];
            g_bias4[b*64+t] = b4[t] + sb*w4[128*64 + t];
        }
    }
}

// ---------------- separable bicubic 2x upsample (NCHW) ----------------
__global__ void upsample_kernel(const float* __restrict__ x){
    int idx = blockIdx.x*256 + threadIdx.x;
    int kw = idx & 127;
    int kh = (idx >> 7) & 127;
    int pl = idx >> 14;
    const float* xp = x + (size_t)pl*16384;
    float* op = g_xu + (size_t)pl*65536;

    int rr[5], cc[5];
    #pragma unroll
    for (int i = 0; i < 5; i++){
        int r = kh - 2 + i; rr[i] = min(max(r,0),127);
        int c = kw - 2 + i; cc[i] = min(max(c,0),127);
    }
    const float we0=-0.03515625f, we1=0.26171875f, we2=0.87890625f, we3=-0.10546875f;
    const float wo0=-0.10546875f, wo1=0.87890625f, wo2=0.26171875f, wo3=-0.03515625f;

    float he[5], ho[5];
    #pragma unroll
    for (int i = 0; i < 5; i++){
        const float* row = xp + rr[i]*128;
        float v0=row[cc[0]], v1=row[cc[1]], v2=row[cc[2]], v3=row[cc[3]], v4=row[cc[4]];
        he[i] = we0*v0 + we1*v1 + we2*v2 + we3*v3;
        ho[i] = wo0*v1 + wo1*v2 + wo2*v3 + wo3*v4;
    }
    float o00 = we0*he[0]+we1*he[1]+we2*he[2]+we3*he[3];
    float o01 = we0*ho[0]+we1*ho[1]+we2*ho[2]+we3*ho[3];
    float o10 = wo0*he[1]+wo1*he[2]+wo2*he[3]+wo3*he[4];
    float o11 = wo0*ho[1]+wo1*ho[2]+wo2*ho[3]+wo3*ho[4];

    *(float2*)(op + (2*kh  )*256 + 2*kw) = make_float2(o00, o01);
    *(float2*)(op + (2*kh+1)*256 + 2*kw) = make_float2(o10, o11);
}

// ---------------- xu NCHW -> xuT NHWC with tf32 rounding ----------------
__global__ void xut_kernel(){
    __shared__ float tile[32][33];
    int w0 = blockIdx.x*32, c0 = blockIdx.y*32;
    int bh = blockIdx.z;
    int b = bh >> 8, h = bh & 255;
    int tx = threadIdx.x, ty = threadIdx.y;
    #pragma unroll
    for (int k = 0; k < 4; k++){
        int c = c0 + ty + k*8;
        tile[ty + k*8][tx] = to_tf32(g_xu[(((size_t)b*256 + c)*256 + h)*256 + w0 + tx]);
    }
    __syncthreads();
    #pragma unroll
    for (int k = 0; k < 4; k++){
        int w = w0 + ty + k*8;
        g_xuT[(((size_t)b*256 + h)*256 + w)*256 + c0 + tx] = tile[tx][ty + k*8];
    }
}

// ---------------- y NCHW -> f NHWC (channels 128..255) ----------------
__global__ void ycopy_kernel(const float* __restrict__ y){
    __shared__ float tile[32][33];
    int w0 = blockIdx.x*32, c0 = blockIdx.y*32;
    int bh = blockIdx.z;
    int b = bh >> 8, h = bh & 255;
    int tx = threadIdx.x, ty = threadIdx.y;
    #pragma unroll
    for (int k = 0; k < 4; k++){
        int c = c0 + ty + k*8;
        tile[ty + k*8][tx] = y[(((size_t)b*128 + c)*256 + h)*256 + w0 + tx];
    }
    __syncthreads();
    #pragma unroll
    for (int k = 0; k < 4; k++){
        int w = w0 + ty + k*8;
        g_f[(((size_t)b*256 + h)*256 + w)*256 + 128 + c0 + tx] = tile[tx][ty + k*8];
    }
}

// ---------------- conv 3x3 via tf32 mma.sync: CTA tile 128 pixels x 128 co ----------------
// 8 warps: 2(M) x 4(N); warp tile 64x32 = 4x4 m16n8k8 fragments.
// Shared stride 136 floats: fragment loads AND transposing fills are conflict-free.
__global__ __launch_bounds__(256) void conv_mma_kernel(const float* __restrict__ convb){
    __shared__ float As[32][136];
    __shared__ float Bs[32][136];

    int bx = blockIdx.x;
    int w0 = (bx & 1)*128;
    int h  = (bx >> 1) & 255;
    int b  = bx >> 9;
    int tid = threadIdx.x;
    int wid = tid >> 5, lane = tid & 31;
    int wm = wid & 1, wn = wid >> 1;
    int lr = lane >> 2, lc = lane & 3;       // fragment row/col
    int pr = tid & 127, qb = tid >> 7;       // fill: pixel/co row, quad base

    float acc[4][4][4];
    #pragma unroll
    for (int mi = 0; mi < 4; mi++)
        #pragma unroll
        for (int ni = 0; ni < 4; ni++)
            #pragma unroll
            for (int r = 0; r < 4; r++) acc[mi][ni][r] = 0.f;

    bool first_sync = true;
    for (int off = 0; off < 9; off++){
        int dh = off/3 - 1, dw = off%3 - 1;
        int hh = h + dh;
        if (hh < 0 || hh >= HH) continue;
        const float* abase = g_xuT + (((size_t)b*256 + hh)*256)*256;
        const float* wbase = g_w9t + (size_t)off*32768;
        int w_in = w0 + pr + dw;
        bool wok = (w_in >= 0) && (w_in < WWD);
        const float* aptr = abase + (size_t)w_in*256;

        for (int c8 = 0; c8 < 8; c8++){
            int ci0 = c8*32;
            if (!first_sync) __syncthreads();
            first_sync = false;

            // fill A: 128 pixels x 32 ci (transpose NHWC float4 -> As[k][m])
            #pragma unroll
            for (int q = 0; q < 4; q++){
                int qq = qb + 2*q;
                float4 v = make_float4(0.f,0.f,0.f,0.f);
                if (wok) v = *(const float4*)(aptr + ci0 + qq*4);
                As[qq*4+0][pr] = v.x;
                As[qq*4+1][pr] = v.y;
                As[qq*4+2][pr] = v.z;
                As[qq*4+3][pr] = v.w;
            }
            // fill B: 128 co x 32 ci (transpose [co][ci] float4 -> Bs[k][n])
            #pragma unroll
            for (int q = 0; q < 4; q++){
                int qq = qb + 2*q;
                float4 v = *(const float4*)(wbase + pr*256 + ci0 + qq*4);
                Bs[qq*4+0][pr] = v.x;
                Bs[qq*4+1][pr] = v.y;
                Bs[qq*4+2][pr] = v.z;
                Bs[qq*4+3][pr] = v.w;
            }
            __syncthreads();

            #pragma unroll
            for (int ks = 0; ks < 4; ks++){
                int kb = ks*8;
                uint32_t a[4][4];
                #pragma unroll
                for (int mi = 0; mi < 4; mi++){
                    int mb = wm*64 + mi*16;
                    a[mi][0] = __float_as_uint(As[kb + lc    ][mb + lr    ]);
                    a[mi][1] = __float_as_uint(As[kb + lc    ][mb + lr + 8]);
                    a[mi][2] = __float_as_uint(As[kb + lc + 4][mb + lr    ]);
                    a[mi][3] = __float_as_uint(As[kb + lc + 4][mb + lr + 8]);
                }
                uint32_t bf[4][2];
                #pragma unroll
                for (int ni = 0; ni < 4; ni++){
                    int nb = wn*32 + ni*8;
                    bf[ni][0] = __float_as_uint(Bs[kb + lc    ][nb + lr]);
                    bf[ni][1] = __float_as_uint(Bs[kb + lc + 4][nb + lr]);
                }
                #pragma unroll
                for (int mi = 0; mi < 4; mi++)
                    #pragma unroll
                    for (int ni = 0; ni < 4; ni++)
                        mma_tf32(acc[mi][ni],
                                 a[mi][0], a[mi][1], a[mi][2], a[mi][3],
                                 bf[ni][0], bf[ni][1]);
            }
        }
    }

    // epilogue: bias + store to g_f channels 0..127 (NHWC)
    float bv0[4], bv1[4];
    #pragma unroll
    for (int ni = 0; ni < 4; ni++){
        int n = wn*32 + ni*8 + lc*2;
        bv0[ni] = convb[n];
        bv1[ni] = convb[n+1];
    }
    #pragma unroll
    for (int mi = 0; mi < 4; mi++){
        int m0 = wm*64 + mi*16 + lr;
        float* dst0 = g_f + (((size_t)b*256 + h)*256 + w0 + m0    )*256;
        float* dst1 = g_f + (((size_t)b*256 + h)*256 + w0 + m0 + 8)*256;
        #pragma unroll
        for (int ni = 0; ni < 4; ni++){
            int n = wn*32 + ni*8 + lc*2;
            *(float2*)(dst0 + n) = make_float2(acc[mi][ni][0] + bv0[ni],
                                               acc[mi][ni][1] + bv1[ni]);
            *(float2*)(dst1 + n) = make_float2(acc[mi][ni][2] + bv0[ni],
                                               acc[mi][ni][3] + bv1[ni]);
        }
    }
}

// ---------------- generic tiled fp32 SGEMM ----------------
template<int K, int N, int EPI>
__global__ __launch_bounds__(256) void gemm_kernel(
    const float* __restrict__ A, const float* __restrict__ Wt,
    const float* __restrict__ bias, float* __restrict__ out,
    const float* __restrict__ identity)
{
    constexpr int TN  = N/16;
    constexpr int NB4 = N/4;
    constexpr int KKP = 256/NB4;
    __shared__ float As[32][128];
    __shared__ float Bs[32][N];

    int m0  = blockIdx.x*128;
    int tid = threadIdx.x;
    int tx = tid & 15, ty = tid >> 4;
    int rowA = tid >> 3, kqA = tid & 7;
    int kkB = tid / NB4, nqB = tid % NB4;

    float acc[8][TN];
    #pragma unroll
    for (int i = 0; i < 8; i++)
        #pragma unroll
        for (int j = 0; j < TN; j++) acc[i][j] = 0.f;

    for (int k0 = 0; k0 < K; k0 += 32){
        #pragma unroll
        for (int p = 0; p < 4; p++){
            int r = rowA + p*32;
            float4 v = *(const float4*)&A[(size_t)(m0+r)*K + k0 + kqA*4];
            int kr = kqA*4;
            As[kr+0][r ^ (((kr+0)&7)<<2)] = v.x;
            As[kr+1][r ^ (((kr+1)&7)<<2)] = v.y;
            As[kr+2][r ^ (((kr+2)&7)<<2)] = v.z;
            As[kr+3][r ^ (((kr+3)&7)<<2)] = v.w;
        }
        #pragma unroll
        for (int p = 0; p < 32/KKP; p++){
            int kk = kkB + p*KKP;
            *(float4*)&Bs[kk][nqB*4] = *(const float4*)&Wt[(size_t)(k0+kk)*N + nqB*4];
        }
        __syncthreads();
        #pragma unroll
        for (int kk = 0; kk < 32; kk++){
            int sw = (kk & 7) << 2;
            float a[8], bb[TN];
            *(float4*)&a[0] = *(float4*)&As[kk][(ty*8  ) ^ sw];
            *(float4*)&a[4] = *(float4*)&As[kk][(ty*8+4) ^ sw];
            if constexpr (TN == 8){
                *(float4*)&bb[0] = *(float4*)&Bs[kk][tx*8];
                *(float4*)&bb[4] = *(float4*)&Bs[kk][tx*8+4];
            } else {
                *(float4*)&bb[0] = *(float4*)&Bs[kk][tx*4];
            }
            #pragma unroll
            for (int i = 0; i < 8; i++)
                #pragma unroll
                for (int j = 0; j < TN; j++)
                    acc[i][j] = fmaf(a[i], bb[j], acc[i][j]);
        }
        __syncthreads();
    }

    int b = m0 >> 16;
    const float* bp = (EPI == 0 || EPI == 4) ? (bias + b*N) : bias;
    float bv[TN];
    #pragma unroll
    for (int j = 0; j < TN; j++) bv[j] = bp[tx*TN + j];

    #pragma unroll
    for (int i = 0; i < 8; i++){
        int m = m0 + ty*8 + i;
        if constexpr (EPI == 3){
            int hw = m & 65535;
            #pragma unroll
            for (int j = 0; j < TN; j++){
                int n = tx*TN + j;
                float v = fmaxf(acc[i][j] + bv[j], 0.f)
                        + identity[(size_t)m*128 + n];
                out[((size_t)(b*128 + n))*65536 + hw] = v;
            }
        } else {
            float* dst = out + (size_t)m*N + tx*TN;
            #pragma unroll
            for (int j = 0; j < TN; j += 4){
                float4 v;
                v.x = acc[i][j+0] + bv[j+0];
                v.y = acc[i][j+1] + bv[j+1];
                v.z = acc[i][j+2] + bv[j+2];
                v.w = acc[i][j+3] + bv[j+3];
                if (EPI == 2 || EPI == 4){
                    v.x = fmaxf(v.x,0.f); v.y = fmaxf(v.y,0.f);
                    v.z = fmaxf(v.z,0.f); v.w = fmaxf(v.w,0.f);
                }
                *(float4*)&dst[j] = v;
            }
        }
    }
}

// ---------------- deterministic layernorm ----------------
__global__ void ln_part(){
    int b = blockIdx.y, blk = blockIdx.x, tid = threadIdx.x;
    const float4* p = (const float4*)(g_h1 + (size_t)b*8388608 + (size_t)blk*16384);
    float s = 0.f, s2 = 0.f;
    for (int i = tid; i < 4096; i += 256){
        float4 v = p[i];
        s  += v.x + v.y + v.z + v.w;
        s2 += v.x*v.x + v.y*v.y + v.z*v.z + v.w*v.w;
    }
    __shared__ float sh[256], sh2[256];
    sh[tid] = s; sh2[tid] = s2; __syncthreads();
    for (int st = 128; st > 0; st >>= 1){
        if (tid < st){ sh[tid] += sh[tid+st]; sh2[tid] += sh2[tid+st]; }
        __syncthreads();
    }
    if (tid == 0){
        g_part[(b*512 + blk)*2    ] = sh[0];
        g_part[(b*512 + blk)*2 + 1] = sh2[0];
    }
}

__global__ void ln_finish(){
    int b = blockIdx.x, tid = threadIdx.x;
    float s = 0.f, s2 = 0.f;
    for (int i = tid; i < 512; i += 256){
        s  += g_part[(b*512 + i)*2];
        s2 += g_part[(b*512 + i)*2 + 1];
    }
    __shared__ float sh[256], sh2[256];
    sh[tid] = s; sh2[tid] = s2; __syncthreads();
    for (int st = 128; st > 0; st >>= 1){
        if (tid < st){ sh[tid] += sh[tid+st]; sh2[tid] += sh2[tid+st]; }
        __syncthreads();
    }
    if (tid == 0){
        const float invN = 1.f / 8388608.f;
        float mu  = sh[0] * invN;
        float var = sh2[0] * invN - mu*mu;
        g_stats[b*2]     = mu;
        g_stats[b*2 + 1] = rsqrtf(var + 1e-5f);
    }
}

__global__ void ln_apply(const float* __restrict__ lnw, const float* __restrict__ lnb){
    size_t e = ((size_t)blockIdx.x*256 + threadIdx.x)*4;
    int b = (int)(e >> 23);
    float mu = g_stats[b*2], rs = g_stats[b*2 + 1];
    size_t li = e & 8388607u;
    float4 h = *(const float4*)&g_h1[e];
    float4 w = *(const float4*)&lnw[li];
    float4 c = *(const float4*)&lnb[li];
    float4 o;
    o.x = (h.x - mu)*rs*w.x + c.x;
    o.y = (h.y - mu)*rs*w.y + c.y;
    o.z = (h.z - mu)*rs*w.z + c.z;
    o.w = (h.w - mu)*rs*w.w + c.w;
    *(float4*)&g_ln[e] = o;
}

// ---------------- launch ----------------
extern "C" void kernel_launch(void* const* d_in, const int* in_sizes, int n_in,
                              void* d_out, int out_size){
    const float* x      = (const float*)d_in[0];
    const float* y      = (const float*)d_in[1];
    const float* s      = (const float*)d_in[2];
    const float* conv_w = (const float*)d_in[4];
    const float* conv_b = (const float*)d_in[5];
    const float* mlp1_w = (const float*)d_in[6];
    const float* mlp1_b = (const float*)d_in[7];
    const float* ln_w   = (const float*)d_in[8];
    const float* ln_b   = (const float*)d_in[9];
    const float* m3_w1  = (const float*)d_in[10];
    const float* m3_b1  = (const float*)d_in[11];
    const float* m3_w2  = (const float*)d_in[12];
    const float* m3_b2  = (const float*)d_in[13];
    const float* m3_w3  = (const float*)d_in[14];
    const float* m3_b3  = (const float*)d_in[15];
    const float* m4_w1  = (const float*)d_in[16];
    const float* m4_b1  = (const float*)d_in[17];
    const float* m4_w2  = (const float*)d_in[18];
    const float* m4_b2  = (const float*)d_in[19];
    const float* m4_w3  = (const float*)d_in[20];
    const float* m4_b3  = (const float*)d_in[21];
    float* out = (float*)d_out;

    void *pf, *ph1, *pln, *pt1, *pt2, *pt3, *pb1, *pb3, *pb4;
    cudaGetSymbolAddress(&pf,  g_f);
    cudaGetSymbolAddress(&ph1, g_h1);
    cudaGetSymbolAddress(&pln, g_ln);
    cudaGetSymbolAddress(&pt1, g_t1);
    cudaGetSymbolAddress(&pt2, g_t2);
    cudaGetSymbolAddress(&pt3, g_t3);
    cudaGetSymbolAddress(&pb1, g_bias1);
    cudaGetSymbolAddress(&pb3, g_bias3);
    cudaGetSymbolAddress(&pb4, g_bias4);

    prep_w9t<<<1152, 256>>>(conv_w);
    prep_bias<<<1, 256>>>(s, mlp1_w, mlp1_b, m3_w1, m3_b1, m4_w1, m4_b1);
    upsample_kernel<<<131072, 256>>>(x);
    xut_kernel<<<dim3(8, 8, 2048), dim3(32, 8)>>>();
    ycopy_kernel<<<dim3(8, 4, 2048), dim3(32, 8)>>>(y);
    conv_mma_kernel<<<4096, 256>>>(conv_b);

    // mlp1: f(K=256) -> h1(N=128), per-batch bias + relu
    gemm_kernel<256,128,4><<<4096, 256>>>((const float*)pf, mlp1_w,
                                          (const float*)pb1, (float*)ph1, nullptr);
    // layernorm
    ln_part<<<dim3(512, 8), 256>>>();
    ln_finish<<<8, 256>>>();
    ln_apply<<<65536, 256>>>(ln_w, ln_b);

    // mlp3
    gemm_kernel<128,64,0><<<4096, 256>>>((const float*)pln, m3_w1,
                                         (const float*)pb3, (float*)pt1, nullptr);
    gemm_kernel<64,64,1><<<4096, 256>>>((const float*)pt1, m3_w2,
                                        m3_b2, (float*)pt2, nullptr);
    gemm_kernel<64,128,2><<<4096, 256>>>((const float*)pt2, m3_w3,
                                         m3_b3, (float*)pt3, nullptr);
    // mlp4 (+ identity add + NCHW scatter)
    gemm_kernel<128,64,0><<<4096, 256>>>((const float*)pt3, m4_w1,
                                         (const float*)pb4, (float*)pt1, nullptr);
    gemm_kernel<64,64,1><<<4096, 256>>>((const float*)pt1, m4_w2,
                                        m4_b2, (float*)pt2, nullptr);
    gemm_kernel<64,128,3><<<4096, 256>>>((const float*)pt2, m4_w3,
                                         m4_b3, out, (const float*)ph1);
}

// round 5
// speedup vs baseline: 1.8132x; 1.4553x over previous
#include <cuda_runtime.h>
#include <math.h>
#include <stdint.h>

#define BATCH 8
#define UPC   256
#define HH    256
#define WWD   256
#define HWN   65536
#define MTOT  (BATCH*HWN)   // 524288

// ---------------- scratch (static device globals; allocation-free) ----------------
__device__ float g_xu [(size_t)BATCH*UPC*HWN];   // upsampled x, NCHW
__device__ float g_xuP[(size_t)BATCH*HWN*UPC];   // [b][h][c8][w][32] ci-permuted, tf32
__device__ float g_f [(size_t)MTOT*256];         // concat(xc, y), NHWC
__device__ float g_h1[(size_t)MTOT*128];
__device__ float g_ln[(size_t)MTOT*128];
__device__ float g_t1[(size_t)MTOT*64];
__device__ float g_t2[(size_t)MTOT*64];
__device__ float g_t3[(size_t)MTOT*128];
__device__ float g_w9p[9*8*128*32];              // [off][c8][co][32] ci-permuted, tf32
__device__ float g_bias1[BATCH*128];
__device__ float g_bias3[BATCH*64];
__device__ float g_bias4[BATCH*64];
__device__ float g_part[BATCH*512*2];
__device__ float g_stats[BATCH*2];

__device__ __forceinline__ float to_tf32(float x){
    float r; asm("cvt.rna.tf32.f32 %0, %1;" : "=f"(r) : "f"(x)); return r;
}

__device__ __forceinline__ void mma_tf32(float c[4],
        uint32_t a0, uint32_t a1, uint32_t a2, uint32_t a3,
        uint32_t b0, uint32_t b1){
    asm volatile(
        "mma.sync.aligned.m16n8k8.row.col.f32.tf32.tf32.f32 "
        "{%0,%1,%2,%3}, {%4,%5,%6,%7}, {%8,%9}, {%0,%1,%2,%3};"
        : "+f"(c[0]), "+f"(c[1]), "+f"(c[2]), "+f"(c[3])
        : "r"(a0), "r"(a1), "r"(a2), "r"(a3), "r"(b0), "r"(b1));
}

// permute within each k8 group: kk -> 2*(kk&3) + (kk>>2)
__device__ __forceinline__ int permci(int j){
    return 8*(j>>3) + 2*(j&3) + ((j&7)>>2);
}

// ---------------- prep: conv weight repack (permuted tf32) + s-folded biases ----------------
__global__ void prep_w9p(const float* __restrict__ cw){
    int i = blockIdx.x*256 + threadIdx.x;   // 294912 output slots
    if (i < 9*8*128*32){
        int p   = i & 31;
        int co  = (i >> 5) & 127;
        int c8  = (i >> 12) & 7;
        int off = i >> 15;
        // invert permute: position p holds original kk = ((p&7)>>1) + 4*(p&1)
        int g  = p >> 3, pg = p & 7;
        int j  = 8*g + (pg >> 1) + 4*(pg & 1);
        int ci = c8*32 + j;
        g_w9p[i] = to_tf32(cw[(co*256 + ci)*9 + off]);
    }
}

__global__ void prep_bias(const float* __restrict__ s,
                          const float* __restrict__ m1w, const float* __restrict__ m1b,
                          const float* __restrict__ w3,  const float* __restrict__ b3,
                          const float* __restrict__ w4,  const float* __restrict__ b4){
    int t = threadIdx.x;
    for (int b = 0; b < BATCH; b++){
        float sb = s[b];
        if (t < 128) g_bias1[b*128+t] = m1b[t] + sb*m1w[256*128 + t];
        if (t < 64){
            g_bias3[b*64+t] = b3[t] + sb*w3[128*64 + t];
            g_bias4[b*64+t] = b4[t] + sb*w4[128*64 + t];
        }
    }
}

// ---------------- separable bicubic 2x upsample (NCHW) ----------------
__global__ void upsample_kernel(const float* __restrict__ x){
    int idx = blockIdx.x*256 + threadIdx.x;
    int kw = idx & 127;
    int kh = (idx >> 7) & 127;
    int pl = idx >> 14;
    const float* xp = x + (size_t)pl*16384;
    float* op = g_xu + (size_t)pl*65536;

    int rr[5], cc[5];
    #pragma unroll
    for (int i = 0; i < 5; i++){
        int r = kh - 2 + i; rr[i] = min(max(r,0),127);
        int c = kw - 2 + i; cc[i] = min(max(c,0),127);
    }
    const float we0=-0.03515625f, we1=0.26171875f, we2=0.87890625f, we3=-0.10546875f;
    const float wo0=-0.10546875f, wo1=0.87890625f, wo2=0.26171875f, wo3=-0.03515625f;

    float he[5], ho[5];
    #pragma unroll
    for (int i = 0; i < 5; i++){
        const float* row = xp + rr[i]*128;
        float v0=row[cc[0]], v1=row[cc[1]], v2=row[cc[2]], v3=row[cc[3]], v4=row[cc[4]];
        he[i] = we0*v0 + we1*v1 + we2*v2 + we3*v3;
        ho[i] = wo0*v1 + wo1*v2 + wo2*v3 + wo3*v4;
    }
    float o00 = we0*he[0]+we1*he[1]+we2*he[2]+we3*he[3];
    float o01 = we0*ho[0]+we1*ho[1]+we2*ho[2]+we3*ho[3];
    float o10 = wo0*he[1]+wo1*he[2]+wo2*he[3]+wo3*he[4];
    float o11 = wo0*ho[1]+wo1*ho[2]+wo2*ho[3]+wo3*ho[4];

    *(float2*)(op + (2*kh  )*256 + 2*kw) = make_float2(o00, o01);
    *(float2*)(op + (2*kh+1)*256 + 2*kw) = make_float2(o10, o11);
}

// ---------------- xu NCHW -> xuP [b][h][c8][w][32-permuted] with tf32 rounding ----------------
__global__ void xup_kernel(){
    __shared__ float tile[32][33];
    int w0 = blockIdx.x*32, c8 = blockIdx.y;
    int bh = blockIdx.z;
    int b = bh >> 8, h = bh & 255;
    int tx = threadIdx.x, ty = threadIdx.y;
    int c0 = c8*32;
    #pragma unroll
    for (int k = 0; k < 4; k++){
        int c = c0 + ty + k*8;
        tile[ty + k*8][tx] = to_tf32(g_xu[(((size_t)b*256 + c)*256 + h)*256 + w0 + tx]);
    }
    __syncthreads();
    int pp = permci(tx);
    float* obase = g_xuP + (((size_t)(b*256 + h)*8 + c8)*256)*32;
    #pragma unroll
    for (int k = 0; k < 4; k++){
        int w = w0 + ty + k*8;
        obase[w*32 + pp] = tile[tx][ty + k*8];
    }
}

// ---------------- y NCHW -> f NHWC (channels 128..255) ----------------
__global__ void ycopy_kernel(const float* __restrict__ y){
    __shared__ float tile[32][33];
    int w0 = blockIdx.x*32, c0 = blockIdx.y*32;
    int bh = blockIdx.z;
    int b = bh >> 8, h = bh & 255;
    int tx = threadIdx.x, ty = threadIdx.y;
    #pragma unroll
    for (int k = 0; k < 4; k++){
        int c = c0 + ty + k*8;
        tile[ty + k*8][tx] = y[(((size_t)b*128 + c)*256 + h)*256 + w0 + tx];
    }
    __syncthreads();
    #pragma unroll
    for (int k = 0; k < 4; k++){
        int w = w0 + ty + k*8;
        g_f[(((size_t)b*256 + h)*256 + w)*256 + 128 + c0 + tx] = tile[tx][ty + k*8];
    }
}

// ---------------- conv 3x3 via tf32 mma.sync, dh-major with 3-dw A reuse ----------------
// CTA: 128 pixels x 128 co; 4 warps 2(M)x2(N), warp tile 64x64 (4x8 m16n8k8 frags).
// SMEM: As[130][40] pixels(+halo) x 32ci-permuted; Bs[3*128][40] (dw,co) x 32ci-permuted.
#define AS_FLOATS (130*40)
#define BS_FLOATS (384*40)
#define CONV_SMEM ((AS_FLOATS + BS_FLOATS)*4)   // 82240 bytes

__global__ __launch_bounds__(128, 2) void conv_mma_kernel(const float* __restrict__ convb){
    extern __shared__ float cs[];
    float* As = cs;
    float* Bs = cs + AS_FLOATS;

    int bx = blockIdx.x;
    int w0 = (bx & 1)*128;
    int h  = (bx >> 1) & 255;
    int b  = bx >> 9;
    int tid = threadIdx.x;
    int wid = tid >> 5, lane = tid & 31;
    int wm = wid & 1, wn = wid >> 1;
    int lr = lane >> 2, lc = lane & 3;
    int frow = lane >> 3, fq = lane & 7;

    float acc[4][8][4];
    #pragma unroll
    for (int mi = 0; mi < 4; mi++)
        #pragma unroll
        for (int ni = 0; ni < 8; ni++)
            #pragma unroll
            for (int r = 0; r < 4; r++) acc[mi][ni][r] = 0.f;

    bool first = true;
    for (int dh = -1; dh <= 1; dh++){
        int hh = h + dh;
        if (hh < 0 || hh >= HH) continue;
        const float* aplane = g_xuP + (((size_t)(b*256 + hh)*8)*256)*32;
        int off3 = (dh+1)*3;

        for (int c8 = 0; c8 < 8; c8++){
            if (!first) __syncthreads();
            first = false;

            // fill A: 130 rows x 32 floats (straight float4 copy, zero halo)
            const float* ap = aplane + c8*8192;
            #pragma unroll
            for (int r = 0; r < 9; r++){
                int row = r*16 + wid*4 + frow;
                if (row < 130){
                    int w_in = w0 - 1 + row;
                    float4 v = make_float4(0.f,0.f,0.f,0.f);
                    if (w_in >= 0 && w_in < WWD)
                        v = *(const float4*)(ap + w_in*32 + fq*4);
                    *(float4*)(As + row*40 + fq*4) = v;
                }
            }
            // fill B: 3 dw x 128 co x 32 floats
            #pragma unroll
            for (int r = 0; r < 24; r++){
                int flat = r*16 + wid*4 + frow;     // 0..383
                int dwi = flat >> 7, co = flat & 127;
                float4 v = *(const float4*)(g_w9p +
                            (((size_t)(off3 + dwi)*8 + c8)*128 + co)*32 + fq*4);
                *(float4*)(Bs + flat*40 + fq*4) = v;
            }
            __syncthreads();

            // compute: 3 dw passes x 4 k-steps
            #pragma unroll
            for (int dwi = 0; dwi < 3; dwi++){
                #pragma unroll
                for (int ks = 0; ks < 4; ks++){
                    float2 af[4][2];
                    #pragma unroll
                    for (int mi = 0; mi < 4; mi++){
                        int mrow = wm*64 + mi*16 + lr + dwi;
                        af[mi][0] = *(float2*)(As + mrow*40     + ks*8 + 2*lc);
                        af[mi][1] = *(float2*)(As + (mrow+8)*40 + ks*8 + 2*lc);
                    }
                    float2 bf[8];
                    #pragma unroll
                    for (int ni = 0; ni < 8; ni++){
                        int nrow = dwi*128 + wn*64 + ni*8 + lr;
                        bf[ni] = *(float2*)(Bs + nrow*40 + ks*8 + 2*lc);
                    }
                    #pragma unroll
                    for (int mi = 0; mi < 4; mi++)
                        #pragma unroll
                        for (int ni = 0; ni < 8; ni++)
                            mma_tf32(acc[mi][ni],
                                __float_as_uint(af[mi][0].x), __float_as_uint(af[mi][1].x),
                                __float_as_uint(af[mi][0].y), __float_as_uint(af[mi][1].y),
                                __float_as_uint(bf[ni].x),    __float_as_uint(bf[ni].y));
                }
            }
        }
    }

    // epilogue: bias + store to g_f channels 0..127 (NHWC)
    float bv0[8], bv1[8];
    #pragma unroll
    for (int ni = 0; ni < 8; ni++){
        int n = wn*64 + ni*8 + lc*2;
        bv0[ni] = convb[n];
        bv1[ni] = convb[n+1];
    }
    #pragma unroll
    for (int mi = 0; mi < 4; mi++){
        int m0 = wm*64 + mi*16 + lr;
        float* dst0 = g_f + (((size_t)b*256 + h)*256 + w0 + m0    )*256;
        float* dst1 = g_f + (((size_t)b*256 + h)*256 + w0 + m0 + 8)*256;
        #pragma unroll
        for (int ni = 0; ni < 8; ni++){
            int n = wn*64 + ni*8 + lc*2;
            *(float2*)(dst0 + n) = make_float2(acc[mi][ni][0] + bv0[ni],
                                               acc[mi][ni][1] + bv1[ni]);
            *(float2*)(dst1 + n) = make_float2(acc[mi][ni][2] + bv0[ni],
                                               acc[mi][ni][3] + bv1[ni]);
        }
    }
}

// ---------------- generic tiled fp32 SGEMM ----------------
template<int K, int N, int EPI>
__global__ __launch_bounds__(256) void gemm_kernel(
    const float* __restrict__ A, const float* __restrict__ Wt,
    const float* __restrict__ bias, float* __restrict__ out,
    const float* __restrict__ identity)
{
    constexpr int TN  = N/16;
    constexpr int NB4 = N/4;
    constexpr int KKP = 256/NB4;
    __shared__ float As[32][128];
    __shared__ float Bs[32][N];

    int m0  = blockIdx.x*128;
    int tid = threadIdx.x;
    int tx = tid & 15, ty = tid >> 4;
    int rowA = tid >> 3, kqA = tid & 7;
    int kkB = tid / NB4, nqB = tid % NB4;

    float acc[8][TN];
    #pragma unroll
    for (int i = 0; i < 8; i++)
        #pragma unroll
        for (int j = 0; j < TN; j++) acc[i][j] = 0.f;

    for (int k0 = 0; k0 < K; k0 += 32){
        #pragma unroll
        for (int p = 0; p < 4; p++){
            int r = rowA + p*32;
            float4 v = *(const float4*)&A[(size_t)(m0+r)*K + k0 + kqA*4];
            int kr = kqA*4;
            As[kr+0][r ^ (((kr+0)&7)<<2)] = v.x;
            As[kr+1][r ^ (((kr+1)&7)<<2)] = v.y;
            As[kr+2][r ^ (((kr+2)&7)<<2)] = v.z;
            As[kr+3][r ^ (((kr+3)&7)<<2)] = v.w;
        }
        #pragma unroll
        for (int p = 0; p < 32/KKP; p++){
            int kk = kkB + p*KKP;
            *(float4*)&Bs[kk][nqB*4] = *(const float4*)&Wt[(size_t)(k0+kk)*N + nqB*4];
        }
        __syncthreads();
        #pragma unroll
        for (int kk = 0; kk < 32; kk++){
            int sw = (kk & 7) << 2;
            float a[8], bb[TN];
            *(float4*)&a[0] = *(float4*)&As[kk][(ty*8  ) ^ sw];
            *(float4*)&a[4] = *(float4*)&As[kk][(ty*8+4) ^ sw];
            if constexpr (TN == 8){
                *(float4*)&bb[0] = *(float4*)&Bs[kk][tx*8];
                *(float4*)&bb[4] = *(float4*)&Bs[kk][tx*8+4];
            } else {
                *(float4*)&bb[0] = *(float4*)&Bs[kk][tx*4];
            }
            #pragma unroll
            for (int i = 0; i < 8; i++)
                #pragma unroll
                for (int j = 0; j < TN; j++)
                    acc[i][j] = fmaf(a[i], bb[j], acc[i][j]);
        }
        __syncthreads();
    }

    int b = m0 >> 16;
    const float* bp = (EPI == 0 || EPI == 4) ? (bias + b*N) : bias;
    float bv[TN];
    #pragma unroll
    for (int j = 0; j < TN; j++) bv[j] = bp[tx*TN + j];

    #pragma unroll
    for (int i = 0; i < 8; i++){
        int m = m0 + ty*8 + i;
        if constexpr (EPI == 3){
            int hw = m & 65535;
            #pragma unroll
            for (int j = 0; j < TN; j++){
                int n = tx*TN + j;
                float v = fmaxf(acc[i][j] + bv[j], 0.f)
                        + identity[(size_t)m*128 + n];
                out[((size_t)(b*128 + n))*65536 + hw] = v;
            }
        } else {
            float* dst = out + (size_t)m*N + tx*TN;
            #pragma unroll
            for (int j = 0; j < TN; j += 4){
                float4 v;
                v.x = acc[i][j+0] + bv[j+0];
                v.y = acc[i][j+1] + bv[j+1];
                v.z = acc[i][j+2] + bv[j+2];
                v.w = acc[i][j+3] + bv[j+3];
                if (EPI == 2 || EPI == 4){
                    v.x = fmaxf(v.x,0.f); v.y = fmaxf(v.y,0.f);
                    v.z = fmaxf(v.z,0.f); v.w = fmaxf(v.w,0.f);
                }
                *(float4*)&dst[j] = v;
            }
        }
    }
}

// ---------------- deterministic layernorm ----------------
__global__ void ln_part(){
    int b = blockIdx.y, blk = blockIdx.x, tid = threadIdx.x;
    const float4* p = (const float4*)(g_h1 + (size_t)b*8388608 + (size_t)blk*16384);
    float s = 0.f, s2 = 0.f;
    for (int i = tid; i < 4096; i += 256){
        float4 v = p[i];
        s  += v.x + v.y + v.z + v.w;
        s2 += v.x*v.x + v.y*v.y + v.z*v.z + v.w*v.w;
    }
    __shared__ float sh[256], sh2[256];
    sh[tid] = s; sh2[tid] = s2; __syncthreads();
    for (int st = 128; st > 0; st >>= 1){
        if (tid < st){ sh[tid] += sh[tid+st]; sh2[tid] += sh2[tid+st]; }
        __syncthreads();
    }
    if (tid == 0){
        g_part[(b*512 + blk)*2    ] = sh[0];
        g_part[(b*512 + blk)*2 + 1] = sh2[0];
    }
}

__global__ void ln_finish(){
    int b = blockIdx.x, tid = threadIdx.x;
    float s = 0.f, s2 = 0.f;
    for (int i = tid; i < 512; i += 256){
        s  += g_part[(b*512 + i)*2];
        s2 += g_part[(b*512 + i)*2 + 1];
    }
    __shared__ float sh[256], sh2[256];
    sh[tid] = s; sh2[tid] = s2; __syncthreads();
    for (int st = 128; st > 0; st >>= 1){
        if (tid < st){ sh[tid] += sh[tid+st]; sh2[tid] += sh2[tid+st]; }
        __syncthreads();
    }
    if (tid == 0){
        const float invN = 1.f / 8388608.f;
        float mu  = sh[0] * invN;
        float var = sh2[0] * invN - mu*mu;
        g_stats[b*2]     = mu;
        g_stats[b*2 + 1] = rsqrtf(var + 1e-5f);
    }
}

__global__ void ln_apply(const float* __restrict__ lnw, const float* __restrict__ lnb){
    size_t e = ((size_t)blockIdx.x*256 + threadIdx.x)*4;
    int b = (int)(e >> 23);
    float mu = g_stats[b*2], rs = g_stats[b*2 + 1];
    size_t li = e & 8388607u;
    float4 h = *(const float4*)&g_h1[e];
    float4 w = *(const float4*)&lnw[li];
    float4 c = *(const float4*)&lnb[li];
    float4 o;
    o.x = (h.x - mu)*rs*w.x + c.x;
    o.y = (h.y - mu)*rs*w.y + c.y;
    o.z = (h.z - mu)*rs*w.z + c.z;
    o.w = (h.w - mu)*rs*w.w + c.w;
    *(float4*)&g_ln[e] = o;
}

// ---------------- launch ----------------
extern "C" void kernel_launch(void* const* d_in, const int* in_sizes, int n_in,
                              void* d_out, int out_size){
    const float* x      = (const float*)d_in[0];
    const float* y      = (const float*)d_in[1];
    const float* s      = (const float*)d_in[2];
    const float* conv_w = (const float*)d_in[4];
    const float* conv_b = (const float*)d_in[5];
    const float* mlp1_w = (const float*)d_in[6];
    const float* mlp1_b = (const float*)d_in[7];
    const float* ln_w   = (const float*)d_in[8];
    const float* ln_b   = (const float*)d_in[9];
    const float* m3_w1  = (const float*)d_in[10];
    const float* m3_b1  = (const float*)d_in[11];
    const float* m3_w2  = (const float*)d_in[12];
    const float* m3_b2  = (const float*)d_in[13];
    const float* m3_w3  = (const float*)d_in[14];
    const float* m3_b3  = (const float*)d_in[15];
    const float* m4_w1  = (const float*)d_in[16];
    const float* m4_b1  = (const float*)d_in[17];
    const float* m4_w2  = (const float*)d_in[18];
    const float* m4_b2  = (const float*)d_in[19];
    const float* m4_w3  = (const float*)d_in[20];
    const float* m4_b3  = (const float*)d_in[21];
    float* out = (float*)d_out;

    cudaFuncSetAttribute(conv_mma_kernel,
                         cudaFuncAttributeMaxDynamicSharedMemorySize, CONV_SMEM);

    void *pf, *ph1, *pln, *pt1, *pt2, *pt3, *pb1, *pb3, *pb4;
    cudaGetSymbolAddress(&pf,  g_f);
    cudaGetSymbolAddress(&ph1, g_h1);
    cudaGetSymbolAddress(&pln, g_ln);
    cudaGetSymbolAddress(&pt1, g_t1);
    cudaGetSymbolAddress(&pt2, g_t2);
    cudaGetSymbolAddress(&pt3, g_t3);
    cudaGetSymbolAddress(&pb1, g_bias1);
    cudaGetSymbolAddress(&pb3, g_bias3);
    cudaGetSymbolAddress(&pb4, g_bias4);

    prep_w9p<<<1152, 256>>>(conv_w);
    prep_bias<<<1, 256>>>(s, mlp1_w, mlp1_b, m3_w1, m3_b1, m4_w1, m4_b1);
    upsample_kernel<<<131072, 256>>>(x);
    xup_kernel<<<dim3(8, 8, 2048), dim3(32, 8)>>>();
    ycopy_kernel<<<dim3(8, 4, 2048), dim3(32, 8)>>>(y);
    conv_mma_kernel<<<4096, 128, CONV_SMEM>>>(conv_b);

    // mlp1: f(K=256) -> h1(N=128), per-batch bias + relu
    gemm_kernel<256,128,4><<<4096, 256>>>((const float*)pf, mlp1_w,
                                          (const float*)pb1, (float*)ph1, nullptr);
    // layernorm
    ln_part<<<dim3(512, 8), 256>>>();
    ln_finish<<<8, 256>>>();
    ln_apply<<<65536, 256>>>(ln_w, ln_b);

    // mlp3
    gemm_kernel<128,64,0><<<4096, 256>>>((const float*)pln, m3_w1,
                                         (const float*)pb3, (float*)pt1, nullptr);
    gemm_kernel<64,64,1><<<4096, 256>>>((const float*)pt1, m3_w2,
                                        m3_b2, (float*)pt2, nullptr);
    gemm_kernel<64,128,2><<<4096, 256>>>((const float*)pt2, m3_w3,
                                         m3_b3, (float*)pt3, nullptr);
    // mlp4 (+ identity add + NCHW scatter)
    gemm_kernel<128,64,0><<<4096, 256>>>((const float*)pt3, m4_w1,
                                         (const float*)pb4, (float*)pt1, nullptr);
    gemm_kernel<64,64,1><<<4096, 256>>>((const float*)pt1, m4_w2,
                                        m4_b2, (float*)pt2, nullptr);
    gemm_kernel<64,128,3><<<4096, 256>>>((const float*)pt2, m4_w3,
                                         m4_b3, out, (const float*)ph1);
}

// round 6
// speedup vs baseline: 2.5408x; 1.4013x over previous
#include <cuda_runtime.h>
#include <cuda_fp16.h>
#include <math.h>
#include <stdint.h>

#define BATCH 8
#define UPC   256
#define HH    256
#define WWD   256
#define HWN   65536
#define MTOT  (BATCH*HWN)   // 524288

// ---------------- scratch (static device globals; allocation-free) ----------------
__device__ float  g_xu  [(size_t)BATCH*UPC*HWN];   // upsampled x, NCHW (fp32)
__device__ __half g_xuPh[(size_t)BATCH*HWN*UPC];   // [b][h][c8][w][32] pair-interleaved half
__device__ __half g_fh  [(size_t)MTOT*256];        // concat(xc,y) NHWC, pair-interleaved half
__device__ float  g_h1[(size_t)MTOT*128];
__device__ float  g_ln[(size_t)MTOT*128];
__device__ float  g_t1[(size_t)MTOT*64];
__device__ float  g_t2[(size_t)MTOT*64];
__device__ float  g_t3[(size_t)MTOT*128];
__device__ __half g_w9ph[9*8*128*32];              // [off][c8][co][32] interleaved half
__device__ __half g_w1h [128*256];                 // mlp1 W^T [n][k-interleaved] half
__device__ float  g_bias1[BATCH*128];
__device__ float  g_bias3[BATCH*64];
__device__ float  g_bias4[BATCH*64];
__device__ float  g_part[BATCH*512*2];
__device__ float  g_stats[BATCH*2];

// channel c (0..31) -> half slot within 32-half chunk (pair-interleaved)
__device__ __forceinline__ int lam32(int c){
    int g  = c >> 4;
    int kp = (c & 15) >> 1;
    int o  = c & 1;
    return 8*(kp & 3) + 4*g + 2*(kp >> 2) + o;
}

__device__ __forceinline__ void mma_fp16(float c[4],
        uint32_t a0, uint32_t a1, uint32_t a2, uint32_t a3,
        uint32_t b0, uint32_t b1){
    asm volatile(
        "mma.sync.aligned.m16n8k16.row.col.f32.f16.f16.f32 "
        "{%0,%1,%2,%3}, {%4,%5,%6,%7}, {%8,%9}, {%0,%1,%2,%3};"
        : "+f"(c[0]), "+f"(c[1]), "+f"(c[2]), "+f"(c[3])
        : "r"(a0), "r"(a1), "r"(a2), "r"(a3), "r"(b0), "r"(b1));
}

// ---------------- prep kernels ----------------
__global__ void prep_w9h(const float* __restrict__ cw){
    int i = blockIdx.x*256 + threadIdx.x;   // 9*8*128*32 = 294912
    if (i < 9*8*128*32){
        int c   = i & 31;
        int co  = (i >> 5) & 127;
        int c8  = (i >> 12) & 7;
        int off = i >> 15;
        int ci  = c8*32 + c;
        g_w9ph[(((off*8 + c8)*128 + co)*32) + lam32(c)] =
            __float2half_rn(cw[(co*256 + ci)*9 + off]);
    }
}

__global__ void prep_w1h(const float* __restrict__ w1){
    int i = blockIdx.x*256 + threadIdx.x;   // 128*256 = 32768
    if (i < 128*256){
        int k = i & 255, n = i >> 8;
        int chunk = k >> 5, c = k & 31;
        g_w1h[n*256 + chunk*32 + lam32(c)] = __float2half_rn(w1[k*128 + n]);
    }
}

__global__ void prep_bias(const float* __restrict__ s,
                          const float* __restrict__ m1w, const float* __restrict__ m1b,
                          const float* __restrict__ w3,  const float* __restrict__ b3,
                          const float* __restrict__ w4,  const float* __restrict__ b4){
    int t = threadIdx.x;
    for (int b = 0; b < BATCH; b++){
        float sb = s[b];
        if (t < 128) g_bias1[b*128+t] = m1b[t] + sb*m1w[256*128 + t];
        if (t < 64){
            g_bias3[b*64+t] = b3[t] + sb*w3[128*64 + t];
            g_bias4[b*64+t] = b4[t] + sb*w4[128*64 + t];
        }
    }
}

// ---------------- separable bicubic 2x upsample (NCHW fp32) ----------------
__global__ void upsample_kernel(const float* __restrict__ x){
    int idx = blockIdx.x*256 + threadIdx.x;
    int kw = idx & 127;
    int kh = (idx >> 7) & 127;
    int pl = idx >> 14;
    const float* xp = x + (size_t)pl*16384;
    float* op = g_xu + (size_t)pl*65536;

    int rr[5], cc[5];
    #pragma unroll
    for (int i = 0; i < 5; i++){
        int r = kh - 2 + i; rr[i] = min(max(r,0),127);
        int c = kw - 2 + i; cc[i] = min(max(c,0),127);
    }
    const float we0=-0.03515625f, we1=0.26171875f, we2=0.87890625f, we3=-0.10546875f;
    const float wo0=-0.10546875f, wo1=0.87890625f, wo2=0.26171875f, wo3=-0.03515625f;

    float he[5], ho[5];
    #pragma unroll
    for (int i = 0; i < 5; i++){
        const float* row = xp + rr[i]*128;
        float v0=row[cc[0]], v1=row[cc[1]], v2=row[cc[2]], v3=row[cc[3]], v4=row[cc[4]];
        he[i] = we0*v0 + we1*v1 + we2*v2 + we3*v3;
        ho[i] = wo0*v1 + wo1*v2 + wo2*v3 + wo3*v4;
    }
    float o00 = we0*he[0]+we1*he[1]+we2*he[2]+we3*he[3];
    float o01 = we0*ho[0]+we1*ho[1]+we2*ho[2]+we3*ho[3];
    float o10 = wo0*he[1]+wo1*he[2]+wo2*he[3]+wo3*he[4];
    float o11 = wo0*ho[1]+wo1*ho[2]+wo2*ho[3]+wo3*ho[4];

    *(float2*)(op + (2*kh  )*256 + 2*kw) = make_float2(o00, o01);
    *(float2*)(op + (2*kh+1)*256 + 2*kw) = make_float2(o10, o11);
}

// ---------------- xu NCHW -> xuPh [b][h][c8][w][32 interleaved] half ----------------
__global__ void xup_kernel(){
    __shared__ float tile[32][33];
    int w0 = blockIdx.x*32, c8 = blockIdx.y;
    int bh = blockIdx.z;
    int b = bh >> 8, h = bh & 255;
    int tx = threadIdx.x, ty = threadIdx.y;
    int c0 = c8*32;
    #pragma unroll
    for (int k = 0; k < 4; k++){
        int c = c0 + ty + k*8;
        tile[ty + k*8][tx] = g_xu[(((size_t)b*256 + c)*256 + h)*256 + w0 + tx];
    }
    __syncthreads();
    int pp = lam32(tx);
    __half* obase = g_xuPh + (((size_t)(b*256 + h)*8 + c8)*256)*32;
    #pragma unroll
    for (int k = 0; k < 4; k++){
        int w = w0 + ty + k*8;
        obase[w*32 + pp] = __float2half_rn(tile[tx][ty + k*8]);
    }
}

// ---------------- y NCHW -> f half (channels 128..255, interleaved slots) ----------------
__global__ void ycopy_kernel(const float* __restrict__ y){
    __shared__ float tile[32][33];
    int w0 = blockIdx.x*32, cb = blockIdx.y;      // cb: 0..3 -> y channels cb*32..
    int bh = blockIdx.z;
    int b = bh >> 8, h = bh & 255;
    int tx = threadIdx.x, ty = threadIdx.y;
    int c0 = cb*32;
    #pragma unroll
    for (int k = 0; k < 4; k++){
        int c = c0 + ty + k*8;
        tile[ty + k*8][tx] = y[(((size_t)b*128 + c)*256 + h)*256 + w0 + tx];
    }
    __syncthreads();
    int slot = (4 + cb)*32 + lam32(tx);
    #pragma unroll
    for (int k = 0; k < 4; k++){
        int w = w0 + ty + k*8;
        g_fh[(((size_t)b*256 + h)*256 + w)*256 + slot] = __float2half_rn(tile[tx][ty + k*8]);
    }
}

// ---------------- conv 3x3 via fp16 mma m16n8k16, dh-major with 3-dw reuse ----------------
// CTA: 128 pixels x 128 co; 4 warps 2(M)x2(N), warp tile 64x64.
// SMEM: As 130 rows x 64B (pixels+halo), Bs 384 rows x 64B ((dw,co)), XOR-swizzled 16B units.
__global__ __launch_bounds__(128, 2) void conv_mma_kernel(const float* __restrict__ convb){
    __shared__ __align__(16) char As[130*64];
    __shared__ __align__(16) char Bs[384*64];

    int bx = blockIdx.x;
    int w0 = (bx & 1)*128;
    int h  = (bx >> 1) & 255;
    int b  = bx >> 9;
    int tid = threadIdx.x;
    int wid = tid >> 5, lane = tid & 31;
    int wm = wid & 1, wn = wid >> 1;
    int lr = lane >> 2, lc = lane & 3;

    float acc[4][8][4];
    #pragma unroll
    for (int mi = 0; mi < 4; mi++)
        #pragma unroll
        for (int ni = 0; ni < 8; ni++)
            #pragma unroll
            for (int r = 0; r < 4; r++) acc[mi][ni][r] = 0.f;

    bool first = true;
    for (int dh = -1; dh <= 1; dh++){
        int hh = h + dh;
        if (hh < 0 || hh >= HH) continue;
        const __half* aplane = g_xuPh + (((size_t)(b*256 + hh)*8)*256)*32;
        int off3 = (dh+1)*3;

        for (int c8 = 0; c8 < 8; c8++){
            if (!first) __syncthreads();
            first = false;

            // fill A: 130 rows x 64B (16B chunks, XOR swizzle)
            const __half* ap = aplane + (size_t)c8*8192;
            #pragma unroll
            for (int p = 0; p < 5; p++){
                int idx = tid + p*128;
                if (idx < 520){
                    int row = idx >> 2, t = idx & 3;
                    int w_in = w0 - 1 + row;
                    uint4 v = make_uint4(0u,0u,0u,0u);
                    if (w_in >= 0 && w_in < WWD)
                        v = *(const uint4*)(ap + w_in*32 + t*8);
                    *(uint4*)(As + row*64 + (16*t ^ ((row & 1) << 5))) = v;
                }
            }
            // fill B: 384 rows x 64B
            #pragma unroll
            for (int p = 0; p < 12; p++){
                int idx = tid + p*128;
                int row = idx >> 2, t = idx & 3;
                int dwi = row >> 7, co = row & 127;
                uint4 v = *(const uint4*)(g_w9ph +
                            ((((size_t)(off3 + dwi)*8 + c8)*128 + co)*32) + t*8);
                *(uint4*)(Bs + row*64 + (16*t ^ ((row & 1) << 5))) = v;
            }
            __syncthreads();

            #pragma unroll
            for (int dwi = 0; dwi < 3; dwi++){
                uint4 bf[8];
                #pragma unroll
                for (int ni = 0; ni < 8; ni++){
                    int brow = dwi*128 + wn*64 + ni*8 + lr;
                    bf[ni] = *(const uint4*)(Bs + brow*64 + (16*lc ^ ((brow & 1) << 5)));
                }
                #pragma unroll
                for (int mi = 0; mi < 4; mi++){
                    int ar0 = wm*64 + mi*16 + lr + dwi;
                    int ar1 = ar0 + 8;
                    uint4 A1 = *(const uint4*)(As + ar0*64 + (16*lc ^ ((ar0 & 1) << 5)));
                    uint4 A2 = *(const uint4*)(As + ar1*64 + (16*lc ^ ((ar1 & 1) << 5)));
                    #pragma unroll
                    for (int ni = 0; ni < 8; ni++){
                        mma_fp16(acc[mi][ni], A1.x, A2.x, A1.y, A2.y, bf[ni].x, bf[ni].y);
                        mma_fp16(acc[mi][ni], A1.z, A2.z, A1.w, A2.w, bf[ni].z, bf[ni].w);
                    }
                }
            }
        }
    }

    // epilogue: bias + store half2 to g_fh channels 0..127 (interleaved slots)
    float bv0[8], bv1[8];
    int slot[8];
    #pragma unroll
    for (int ni = 0; ni < 8; ni++){
        int n = wn*64 + ni*8 + lc*2;
        bv0[ni] = convb[n];
        bv1[ni] = convb[n+1];
        slot[ni] = (n >> 5)*32 + lam32(n & 31);
    }
    #pragma unroll
    for (int mi = 0; mi < 4; mi++){
        int m0 = wm*64 + mi*16 + lr;
        __half* dst0 = g_fh + (((size_t)b*256 + h)*256 + w0 + m0    )*256;
        __half* dst1 = g_fh + (((size_t)b*256 + h)*256 + w0 + m0 + 8)*256;
        #pragma unroll
        for (int ni = 0; ni < 8; ni++){
            *(__half2*)(dst0 + slot[ni]) =
                __floats2half2_rn(acc[mi][ni][0] + bv0[ni], acc[mi][ni][1] + bv1[ni]);
            *(__half2*)(dst1 + slot[ni]) =
                __floats2half2_rn(acc[mi][ni][2] + bv0[ni], acc[mi][ni][3] + bv1[ni]);
        }
    }
}

// ---------------- mlp1 via fp16 mma: M-tile 128, N=128, K=256 ----------------
__global__ __launch_bounds__(128, 2) void mlp1_mma_kernel(){
    __shared__ __align__(16) char As[128*64];
    __shared__ __align__(16) char Bs[128*64];

    int m0  = blockIdx.x*128;
    int tid = threadIdx.x;
    int wid = tid >> 5, lane = tid & 31;
    int wm = wid & 1, wn = wid >> 1;
    int lr = lane >> 2, lc = lane & 3;

    float acc[4][8][4];
    #pragma unroll
    for (int mi = 0; mi < 4; mi++)
        #pragma unroll
        for (int ni = 0; ni < 8; ni++)
            #pragma unroll
            for (int r = 0; r < 4; r++) acc[mi][ni][r] = 0.f;

    for (int chunk = 0; chunk < 8; chunk++){
        if (chunk) __syncthreads();
        #pragma unroll
        for (int p = 0; p < 4; p++){
            int idx = tid + p*128;
            int row = idx >> 2, t = idx & 3;
            uint4 va = *(const uint4*)(g_fh + ((size_t)(m0 + row)*256 + chunk*32) + t*8);
            *(uint4*)(As + row*64 + (16*t ^ ((row & 1) << 5))) = va;
            uint4 vb = *(const uint4*)(g_w1h + (row*256 + chunk*32) + t*8);
            *(uint4*)(Bs + row*64 + (16*t ^ ((row & 1) << 5))) = vb;
        }
        __syncthreads();

        uint4 bf[8];
        #pragma unroll
        for (int ni = 0; ni < 8; ni++){
            int brow = wn*64 + ni*8 + lr;
            bf[ni] = *(const uint4*)(Bs + brow*64 + (16*lc ^ ((brow & 1) << 5)));
        }
        #pragma unroll
        for (int mi = 0; mi < 4; mi++){
            int ar0 = wm*64 + mi*16 + lr;
            int ar1 = ar0 + 8;
            uint4 A1 = *(const uint4*)(As + ar0*64 + (16*lc ^ ((ar0 & 1) << 5)));
            uint4 A2 = *(const uint4*)(As + ar1*64 + (16*lc ^ ((ar1 & 1) << 5)));
            #pragma unroll
            for (int ni = 0; ni < 8; ni++){
                mma_fp16(acc[mi][ni], A1.x, A2.x, A1.y, A2.y, bf[ni].x, bf[ni].y);
                mma_fp16(acc[mi][ni], A1.z, A2.z, A1.w, A2.w, bf[ni].z, bf[ni].w);
            }
        }
    }

    // epilogue: per-batch bias + relu -> h1 fp32 (true channel order)
    int b = m0 >> 16;
    float bv0[8], bv1[8];
    #pragma unroll
    for (int ni = 0; ni < 8; ni++){
        int n = wn*64 + ni*8 + lc*2;
        bv0[ni] = g_bias1[b*128 + n];
        bv1[ni] = g_bias1[b*128 + n + 1];
    }
    #pragma unroll
    for (int mi = 0; mi < 4; mi++){
        int mr = m0 + wm*64 + mi*16 + lr;
        float* dst0 = g_h1 + (size_t)mr*128;
        float* dst1 = g_h1 + (size_t)(mr + 8)*128;
        #pragma unroll
        for (int ni = 0; ni < 8; ni++){
            int n = wn*64 + ni*8 + lc*2;
            *(float2*)(dst0 + n) = make_float2(fmaxf(acc[mi][ni][0] + bv0[ni], 0.f),
                                               fmaxf(acc[mi][ni][1] + bv1[ni], 0.f));
            *(float2*)(dst1 + n) = make_float2(fmaxf(acc[mi][ni][2] + bv0[ni], 0.f),
                                               fmaxf(acc[mi][ni][3] + bv1[ni], 0.f));
        }
    }
}

// ---------------- generic tiled fp32 SGEMM (mlp3/mlp4 chain) ----------------
template<int K, int N, int EPI>
__global__ __launch_bounds__(256) void gemm_kernel(
    const float* __restrict__ A, const float* __restrict__ Wt,
    const float* __restrict__ bias, float* __restrict__ out,
    const float* __restrict__ identity)
{
    constexpr int TN  = N/16;
    constexpr int NB4 = N/4;
    constexpr int KKP = 256/NB4;
    __shared__ float As[32][128];
    __shared__ float Bs[32][N];

    int m0  = blockIdx.x*128;
    int tid = threadIdx.x;
    int tx = tid & 15, ty = tid >> 4;
    int rowA = tid >> 3, kqA = tid & 7;
    int kkB = tid / NB4, nqB = tid % NB4;

    float acc[8][TN];
    #pragma unroll
    for (int i = 0; i < 8; i++)
        #pragma unroll
        for (int j = 0; j < TN; j++) acc[i][j] = 0.f;

    for (int k0 = 0; k0 < K; k0 += 32){
        #pragma unroll
        for (int p = 0; p < 4; p++){
            int r = rowA + p*32;
            float4 v = *(const float4*)&A[(size_t)(m0+r)*K + k0 + kqA*4];
            int kr = kqA*4;
            As[kr+0][r ^ (((kr+0)&7)<<2)] = v.x;
            As[kr+1][r ^ (((kr+1)&7)<<2)] = v.y;
            As[kr+2][r ^ (((kr+2)&7)<<2)] = v.z;
            As[kr+3][r ^ (((kr+3)&7)<<2)] = v.w;
        }
        #pragma unroll
        for (int p = 0; p < 32/KKP; p++){
            int kk = kkB + p*KKP;
            *(float4*)&Bs[kk][nqB*4] = *(const float4*)&Wt[(size_t)(k0+kk)*N + nqB*4];
        }
        __syncthreads();
        #pragma unroll
        for (int kk = 0; kk < 32; kk++){
            int sw = (kk & 7) << 2;
            float a[8], bb[TN];
            *(float4*)&a[0] = *(float4*)&As[kk][(ty*8  ) ^ sw];
            *(float4*)&a[4] = *(float4*)&As[kk][(ty*8+4) ^ sw];
            if constexpr (TN == 8){
                *(float4*)&bb[0] = *(float4*)&Bs[kk][tx*8];
                *(float4*)&bb[4] = *(float4*)&Bs[kk][tx*8+4];
            } else {
                *(float4*)&bb[0] = *(float4*)&Bs[kk][tx*4];
            }
            #pragma unroll
            for (int i = 0; i < 8; i++)
                #pragma unroll
                for (int j = 0; j < TN; j++)
                    acc[i][j] = fmaf(a[i], bb[j], acc[i][j]);
        }
        __syncthreads();
    }

    int b = m0 >> 16;
    const float* bp = (EPI == 0 || EPI == 4) ? (bias + b*N) : bias;
    float bv[TN];
    #pragma unroll
    for (int j = 0; j < TN; j++) bv[j] = bp[tx*TN + j];

    #pragma unroll
    for (int i = 0; i < 8; i++){
        int m = m0 + ty*8 + i;
        if constexpr (EPI == 3){
            int hw = m & 65535;
            #pragma unroll
            for (int j = 0; j < TN; j++){
                int n = tx*TN + j;
                float v = fmaxf(acc[i][j] + bv[j], 0.f)
                        + identity[(size_t)m*128 + n];
                out[((size_t)(b*128 + n))*65536 + hw] = v;
            }
        } else {
            float* dst = out + (size_t)m*N + tx*TN;
            #pragma unroll
            for (int j = 0; j < TN; j += 4){
                float4 v;
                v.x = acc[i][j+0] + bv[j+0];
                v.y = acc[i][j+1] + bv[j+1];
                v.z = acc[i][j+2] + bv[j+2];
                v.w = acc[i][j+3] + bv[j+3];
                if (EPI == 2 || EPI == 4){
                    v.x = fmaxf(v.x,0.f); v.y = fmaxf(v.y,0.f);
                    v.z = fmaxf(v.z,0.f); v.w = fmaxf(v.w,0.f);
                }
                *(float4*)&dst[j] = v;
            }
        }
    }
}

// ---------------- deterministic layernorm ----------------
__global__ void ln_part(){
    int b = blockIdx.y, blk = blockIdx.x, tid = threadIdx.x;
    const float4* p = (const float4*)(g_h1 + (size_t)b*8388608 + (size_t)blk*16384);
    float s = 0.f, s2 = 0.f;
    for (int i = tid; i < 4096; i += 256){
        float4 v = p[i];
        s  += v.x + v.y + v.z + v.w;
        s2 += v.x*v.x + v.y*v.y + v.z*v.z + v.w*v.w;
    }
    __shared__ float sh[256], sh2[256];
    sh[tid] = s; sh2[tid] = s2; __syncthreads();
    for (int st = 128; st > 0; st >>= 1){
        if (tid < st){ sh[tid] += sh[tid+st]; sh2[tid] += sh2[tid+st]; }
        __syncthreads();
    }
    if (tid == 0){
        g_part[(b*512 + blk)*2    ] = sh[0];
        g_part[(b*512 + blk)*2 + 1] = sh2[0];
    }
}

__global__ void ln_finish(){
    int b = blockIdx.x, tid = threadIdx.x;
    float s = 0.f, s2 = 0.f;
    for (int i = tid; i < 512; i += 256){
        s  += g_part[(b*512 + i)*2];
        s2 += g_part[(b*512 + i)*2 + 1];
    }
    __shared__ float sh[256], sh2[256];
    sh[tid] = s; sh2[tid] = s2; __syncthreads();
    for (int st = 128; st > 0; st >>= 1){
        if (tid < st){ sh[tid] += sh[tid+st]; sh2[tid] += sh2[tid+st]; }
        __syncthreads();
    }
    if (tid == 0){
        const float invN = 1.f / 8388608.f;
        float mu  = sh[0] * invN;
        float var = sh2[0] * invN - mu*mu;
        g_stats[b*2]     = mu;
        g_stats[b*2 + 1] = rsqrtf(var + 1e-5f);
    }
}

__global__ void ln_apply(const float* __restrict__ lnw, const float* __restrict__ lnb){
    size_t e = ((size_t)blockIdx.x*256 + threadIdx.x)*4;
    int b = (int)(e >> 23);
    float mu = g_stats[b*2], rs = g_stats[b*2 + 1];
    size_t li = e & 8388607u;
    float4 h = *(const float4*)&g_h1[e];
    float4 w = *(const float4*)&lnw[li];
    float4 c = *(const float4*)&lnb[li];
    float4 o;
    o.x = (h.x - mu)*rs*w.x + c.x;
    o.y = (h.y - mu)*rs*w.y + c.y;
    o.z = (h.z - mu)*rs*w.z + c.z;
    o.w = (h.w - mu)*rs*w.w + c.w;
    *(float4*)&g_ln[e] = o;
}

// ---------------- launch ----------------
extern "C" void kernel_launch(void* const* d_in, const int* in_sizes, int n_in,
                              void* d_out, int out_size){
    const float* x      = (const float*)d_in[0];
    const float* y      = (const float*)d_in[1];
    const float* s      = (const float*)d_in[2];
    const float* conv_w = (const float*)d_in[4];
    const float* conv_b = (const float*)d_in[5];
    const float* mlp1_w = (const float*)d_in[6];
    const float* mlp1_b = (const float*)d_in[7];
    const float* ln_w   = (const float*)d_in[8];
    const float* ln_b   = (const float*)d_in[9];
    const float* m3_w1  = (const float*)d_in[10];
    const float* m3_b1  = (const float*)d_in[11];
    const float* m3_w2  = (const float*)d_in[12];
    const float* m3_b2  = (const float*)d_in[13];
    const float* m3_w3  = (const float*)d_in[14];
    const float* m3_b3  = (const float*)d_in[15];
    const float* m4_w1  = (const float*)d_in[16];
    const float* m4_b1  = (const float*)d_in[17];
    const float* m4_w2  = (const float*)d_in[18];
    const float* m4_b2  = (const float*)d_in[19];
    const float* m4_w3  = (const float*)d_in[20];
    const float* m4_b3  = (const float*)d_in[21];
    float* out = (float*)d_out;

    void *ph1, *pln, *pt1, *pt2, *pt3, *pb3, *pb4;
    cudaGetSymbolAddress(&ph1, g_h1);
    cudaGetSymbolAddress(&pln, g_ln);
    cudaGetSymbolAddress(&pt1, g_t1);
    cudaGetSymbolAddress(&pt2, g_t2);
    cudaGetSymbolAddress(&pt3, g_t3);
    cudaGetSymbolAddress(&pb3, g_bias3);
    cudaGetSymbolAddress(&pb4, g_bias4);

    prep_w9h<<<1152, 256>>>(conv_w);
    prep_w1h<<<128, 256>>>(mlp1_w);
    prep_bias<<<1, 256>>>(s, mlp1_w, mlp1_b, m3_w1, m3_b1, m4_w1, m4_b1);
    upsample_kernel<<<131072, 256>>>(x);
    xup_kernel<<<dim3(8, 8, 2048), dim3(32, 8)>>>();
    ycopy_kernel<<<dim3(8, 4, 2048), dim3(32, 8)>>>(y);
    conv_mma_kernel<<<4096, 128>>>(conv_b);
    mlp1_mma_kernel<<<4096, 128>>>();

    // layernorm
    ln_part<<<dim3(512, 8), 256>>>();
    ln_finish<<<8, 256>>>();
    ln_apply<<<65536, 256>>>(ln_w, ln_b);

    // mlp3 (fp32)
    gemm_kernel<128,64,0><<<4096, 256>>>((const float*)pln, m3_w1,
                                         (const float*)pb3, (float*)pt1, nullptr);
    gemm_kernel<64,64,1><<<4096, 256>>>((const float*)pt1, m3_w2,
                                        m3_b2, (float*)pt2, nullptr);
    gemm_kernel<64,128,2><<<4096, 256>>>((const float*)pt2, m3_w3,
                                         m3_b3, (float*)pt3, nullptr);
    // mlp4 (+ identity add + NCHW scatter)
    gemm_kernel<128,64,0><<<4096, 256>>>((const float*)pt3, m4_w1,
                                         (const float*)pb4, (float*)pt1, nullptr);
    gemm_kernel<64,64,1><<<4096, 256>>>((const float*)pt1, m4_w2,
                                        m4_b2, (float*)pt2, nullptr);
    gemm_kernel<64,128,3><<<4096, 256>>>((const float*)pt2, m4_w3,
                                         m4_b3, out, (const float*)ph1);
}

// round 7
// speedup vs baseline: 3.6473x; 1.4355x over previous
#include <cuda_runtime.h>
#include <cuda_fp16.h>
#include <math.h>
#include <stdint.h>

#define BATCH 8
#define UPC   256
#define HH    256
#define WWD   256
#define HWN   65536
#define MTOT  (BATCH*HWN)   // 524288

// ---------------- scratch (static device globals; allocation-free) ----------------
__device__ float  g_xu  [(size_t)BATCH*UPC*HWN];   // upsampled x, NCHW (fp32)
__device__ __half g_xuPh[(size_t)BATCH*HWN*UPC];   // [b][h][c8][w][32] pair-interleaved half
__device__ __half g_fh  [(size_t)MTOT*256];        // concat(xc,y) NHWC, pair-interleaved half
__device__ float  g_h1 [(size_t)MTOT*128];         // mlp1 out fp32 (LN stats + identity)
__device__ __half g_lnh[(size_t)MTOT*128];         // layernorm out, interleaved half
__device__ __half g_t1h[(size_t)MTOT*64];
__device__ __half g_t2h[(size_t)MTOT*64];
__device__ __half g_t3h[(size_t)MTOT*128];
__device__ __half g_w9ph[9*8*128*32];              // conv weights [off][c8][co][32] interleaved
__device__ __half g_w1h [128*256];                 // mlp1 W^T [n][k-interleaved]
__device__ __half g_w3a[64*128], g_w3b[64*64], g_w3c[128*64];
__device__ __half g_w4a[64*128], g_w4b[64*64], g_w4c[128*64];
__device__ float  g_bias1[BATCH*128];
__device__ float  g_bias3[BATCH*64];
__device__ float  g_bias4[BATCH*64];
__device__ float  g_part[BATCH*512*2];
__device__ float  g_stats[BATCH*2];

// channel c (0..31) -> half slot within 32-half chunk (pair-interleaved)
__device__ __forceinline__ int lam32(int c){
    int g  = c >> 4;
    int kp = (c & 15) >> 1;
    int o  = c & 1;
    return 8*(kp & 3) + 4*g + 2*(kp >> 2) + o;
}

__device__ __forceinline__ void mma_fp16(float c[4],
        uint32_t a0, uint32_t a1, uint32_t a2, uint32_t a3,
        uint32_t b0, uint32_t b1){
    asm volatile(
        "mma.sync.aligned.m16n8k16.row.col.f32.f16.f16.f32 "
        "{%0,%1,%2,%3}, {%4,%5,%6,%7}, {%8,%9}, {%0,%1,%2,%3};"
        : "+f"(c[0]), "+f"(c[1]), "+f"(c[2]), "+f"(c[3])
        : "r"(a0), "r"(a1), "r"(a2), "r"(a3), "r"(b0), "r"(b1));
}

// ---------------- prep kernels ----------------
__global__ void prep_w9h(const float* __restrict__ cw){
    int i = blockIdx.x*256 + threadIdx.x;
    if (i < 9*8*128*32){
        int c   = i & 31;
        int co  = (i >> 5) & 127;
        int c8  = (i >> 12) & 7;
        int off = i >> 15;
        int ci  = c8*32 + c;
        g_w9ph[(((off*8 + c8)*128 + co)*32) + lam32(c)] =
            __float2half_rn(cw[(co*256 + ci)*9 + off]);
    }
}

__global__ void prep_w1h(const float* __restrict__ w1){
    int i = blockIdx.x*256 + threadIdx.x;
    if (i < 128*256){
        int k = i & 255, n = i >> 8;
        g_w1h[n*256 + (k>>5)*32 + lam32(k & 31)] = __float2half_rn(w1[k*128 + n]);
    }
}

// generic W (K rows x N cols, row-major) -> [n][k-interleaved] half
__global__ void prep_wh(const float* __restrict__ w, __half* __restrict__ o,
                        int K, int N){
    int i = blockIdx.x*256 + threadIdx.x;
    if (i < K*N){
        int k = i % K, n = i / K;
        o[n*K + (k>>5)*32 + lam32(k & 31)] = __float2half_rn(w[k*N + n]);
    }
}

__global__ void prep_bias(const float* __restrict__ s,
                          const float* __restrict__ m1w, const float* __restrict__ m1b,
                          const float* __restrict__ w3,  const float* __restrict__ b3,
                          const float* __restrict__ w4,  const float* __restrict__ b4){
    int t = threadIdx.x;
    for (int b = 0; b < BATCH; b++){
        float sb = s[b];
        if (t < 128) g_bias1[b*128+t] = m1b[t] + sb*m1w[256*128 + t];
        if (t < 64){
            g_bias3[b*64+t] = b3[t] + sb*w3[128*64 + t];
            g_bias4[b*64+t] = b4[t] + sb*w4[128*64 + t];
        }
    }
}

// ---------------- separable bicubic 2x upsample (NCHW fp32) ----------------
__global__ void upsample_kernel(const float* __restrict__ x){
    int idx = blockIdx.x*256 + threadIdx.x;
    int kw = idx & 127;
    int kh = (idx >> 7) & 127;
    int pl = idx >> 14;
    const float* xp = x + (size_t)pl*16384;
    float* op = g_xu + (size_t)pl*65536;

    int rr[5], cc[5];
    #pragma unroll
    for (int i = 0; i < 5; i++){
        int r = kh - 2 + i; rr[i] = min(max(r,0),127);
        int c = kw - 2 + i; cc[i] = min(max(c,0),127);
    }
    const float we0=-0.03515625f, we1=0.26171875f, we2=0.87890625f, we3=-0.10546875f;
    const float wo0=-0.10546875f, wo1=0.87890625f, wo2=0.26171875f, wo3=-0.03515625f;

    float he[5], ho[5];
    #pragma unroll
    for (int i = 0; i < 5; i++){
        const float* row = xp + rr[i]*128;
        float v0=row[cc[0]], v1=row[cc[1]], v2=row[cc[2]], v3=row[cc[3]], v4=row[cc[4]];
        he[i] = we0*v0 + we1*v1 + we2*v2 + we3*v3;
        ho[i] = wo0*v1 + wo1*v2 + wo2*v3 + wo3*v4;
    }
    float o00 = we0*he[0]+we1*he[1]+we2*he[2]+we3*he[3];
    float o01 = we0*ho[0]+we1*ho[1]+we2*ho[2]+we3*ho[3];
    float o10 = wo0*he[1]+wo1*he[2]+wo2*he[3]+wo3*he[4];
    float o11 = wo0*ho[1]+wo1*ho[2]+wo2*ho[3]+wo3*ho[4];

    *(float2*)(op + (2*kh  )*256 + 2*kw) = make_float2(o00, o01);
    *(float2*)(op + (2*kh+1)*256 + 2*kw) = make_float2(o10, o11);
}

// ---------------- xu NCHW -> xuPh [b][h][c8][w][32 interleaved] half ----------------
__global__ void xup_kernel(){
    __shared__ float tile[32][33];
    int w0 = blockIdx.x*32, c8 = blockIdx.y;
    int bh = blockIdx.z;
    int b = bh >> 8, h = bh & 255;
    int tx = threadIdx.x, ty = threadIdx.y;
    int c0 = c8*32;
    #pragma unroll
    for (int k = 0; k < 4; k++){
        int c = c0 + ty + k*8;
        tile[ty + k*8][tx] = g_xu[(((size_t)b*256 + c)*256 + h)*256 + w0 + tx];
    }
    __syncthreads();
    int pp = lam32(tx);
    __half* obase = g_xuPh + (((size_t)(b*256 + h)*8 + c8)*256)*32;
    #pragma unroll
    for (int k = 0; k < 4; k++){
        int w = w0 + ty + k*8;
        obase[w*32 + pp] = __float2half_rn(tile[tx][ty + k*8]);
    }
}

// ---------------- y NCHW -> f half (channels 128..255, interleaved slots) ----------------
__global__ void ycopy_kernel(const float* __restrict__ y){
    __shared__ float tile[32][33];
    int w0 = blockIdx.x*32, cb = blockIdx.y;
    int bh = blockIdx.z;
    int b = bh >> 8, h = bh & 255;
    int tx = threadIdx.x, ty = threadIdx.y;
    int c0 = cb*32;
    #pragma unroll
    for (int k = 0; k < 4; k++){
        int c = c0 + ty + k*8;
        tile[ty + k*8][tx] = y[(((size_t)b*128 + c)*256 + h)*256 + w0 + tx];
    }
    __syncthreads();
    int slot = (4 + cb)*32 + lam32(tx);
    #pragma unroll
    for (int k = 0; k < 4; k++){
        int w = w0 + ty + k*8;
        g_fh[(((size_t)b*256 + h)*256 + w)*256 + slot] = __float2half_rn(tile[tx][ty + k*8]);
    }
}

// ---------------- conv 3x3 via fp16 mma m16n8k16, dh-major with 3-dw reuse ----------------
__global__ __launch_bounds__(128, 2) void conv_mma_kernel(const float* __restrict__ convb){
    __shared__ __align__(16) char As[130*64];
    __shared__ __align__(16) char Bs[384*64];

    int bx = blockIdx.x;
    int w0 = (bx & 1)*128;
    int h  = (bx >> 1) & 255;
    int b  = bx >> 9;
    int tid = threadIdx.x;
    int wid = tid >> 5, lane = tid & 31;
    int wm = wid & 1, wn = wid >> 1;
    int lr = lane >> 2, lc = lane & 3;

    float acc[4][8][4];
    #pragma unroll
    for (int mi = 0; mi < 4; mi++)
        #pragma unroll
        for (int ni = 0; ni < 8; ni++)
            #pragma unroll
            for (int r = 0; r < 4; r++) acc[mi][ni][r] = 0.f;

    bool first = true;
    for (int dh = -1; dh <= 1; dh++){
        int hh = h + dh;
        if (hh < 0 || hh >= HH) continue;
        const __half* aplane = g_xuPh + (((size_t)(b*256 + hh)*8)*256)*32;
        int off3 = (dh+1)*3;

        for (int c8 = 0; c8 < 8; c8++){
            if (!first) __syncthreads();
            first = false;

            const __half* ap = aplane + (size_t)c8*8192;
            #pragma unroll
            for (int p = 0; p < 5; p++){
                int idx = tid + p*128;
                if (idx < 520){
                    int row = idx >> 2, t = idx & 3;
                    int w_in = w0 - 1 + row;
                    uint4 v = make_uint4(0u,0u,0u,0u);
                    if (w_in >= 0 && w_in < WWD)
                        v = *(const uint4*)(ap + w_in*32 + t*8);
                    *(uint4*)(As + row*64 + (16*t ^ ((row & 1) << 5))) = v;
                }
            }
            #pragma unroll
            for (int p = 0; p < 12; p++){
                int idx = tid + p*128;
                int row = idx >> 2, t = idx & 3;
                int dwi = row >> 7, co = row & 127;
                uint4 v = *(const uint4*)(g_w9ph +
                            ((((size_t)(off3 + dwi)*8 + c8)*128 + co)*32) + t*8);
                *(uint4*)(Bs + row*64 + (16*t ^ ((row & 1) << 5))) = v;
            }
            __syncthreads();

            #pragma unroll
            for (int dwi = 0; dwi < 3; dwi++){
                uint4 bf[8];
                #pragma unroll
                for (int ni = 0; ni < 8; ni++){
                    int brow = dwi*128 + wn*64 + ni*8 + lr;
                    bf[ni] = *(const uint4*)(Bs + brow*64 + (16*lc ^ ((brow & 1) << 5)));
                }
                #pragma unroll
                for (int mi = 0; mi < 4; mi++){
                    int ar0 = wm*64 + mi*16 + lr + dwi;
                    int ar1 = ar0 + 8;
                    uint4 A1 = *(const uint4*)(As + ar0*64 + (16*lc ^ ((ar0 & 1) << 5)));
                    uint4 A2 = *(const uint4*)(As + ar1*64 + (16*lc ^ ((ar1 & 1) << 5)));
                    #pragma unroll
                    for (int ni = 0; ni < 8; ni++){
                        mma_fp16(acc[mi][ni], A1.x, A2.x, A1.y, A2.y, bf[ni].x, bf[ni].y);
                        mma_fp16(acc[mi][ni], A1.z, A2.z, A1.w, A2.w, bf[ni].z, bf[ni].w);
                    }
                }
            }
        }
    }

    float bv0[8], bv1[8];
    int slot[8];
    #pragma unroll
    for (int ni = 0; ni < 8; ni++){
        int n = wn*64 + ni*8 + lc*2;
        bv0[ni] = convb[n];
        bv1[ni] = convb[n+1];
        slot[ni] = (n >> 5)*32 + lam32(n & 31);
    }
    #pragma unroll
    for (int mi = 0; mi < 4; mi++){
        int m0 = wm*64 + mi*16 + lr;
        __half* dst0 = g_fh + (((size_t)b*256 + h)*256 + w0 + m0    )*256;
        __half* dst1 = g_fh + (((size_t)b*256 + h)*256 + w0 + m0 + 8)*256;
        #pragma unroll
        for (int ni = 0; ni < 8; ni++){
            *(__half2*)(dst0 + slot[ni]) =
                __floats2half2_rn(acc[mi][ni][0] + bv0[ni], acc[mi][ni][1] + bv1[ni]);
            *(__half2*)(dst1 + slot[ni]) =
                __floats2half2_rn(acc[mi][ni][2] + bv0[ni], acc[mi][ni][3] + bv1[ni]);
        }
    }
}

// ---------------- mlp1 via fp16 mma: M-tile 128, N=128, K=256, out fp32 h1 ----------------
__global__ __launch_bounds__(128, 2) void mlp1_mma_kernel(){
    __shared__ __align__(16) char As[128*64];
    __shared__ __align__(16) char Bs[128*64];

    int m0  = blockIdx.x*128;
    int tid = threadIdx.x;
    int wid = tid >> 5, lane = tid & 31;
    int wm = wid & 1, wn = wid >> 1;
    int lr = lane >> 2, lc = lane & 3;

    float acc[4][8][4];
    #pragma unroll
    for (int mi = 0; mi < 4; mi++)
        #pragma unroll
        for (int ni = 0; ni < 8; ni++)
            #pragma unroll
            for (int r = 0; r < 4; r++) acc[mi][ni][r] = 0.f;

    for (int chunk = 0; chunk < 8; chunk++){
        if (chunk) __syncthreads();
        #pragma unroll
        for (int p = 0; p < 4; p++){
            int idx = tid + p*128;
            int row = idx >> 2, t = idx & 3;
            uint4 va = *(const uint4*)(g_fh + ((size_t)(m0 + row)*256 + chunk*32) + t*8);
            *(uint4*)(As + row*64 + (16*t ^ ((row & 1) << 5))) = va;
            uint4 vb = *(const uint4*)(g_w1h + (row*256 + chunk*32) + t*8);
            *(uint4*)(Bs + row*64 + (16*t ^ ((row & 1) << 5))) = vb;
        }
        __syncthreads();

        uint4 bf[8];
        #pragma unroll
        for (int ni = 0; ni < 8; ni++){
            int brow = wn*64 + ni*8 + lr;
            bf[ni] = *(const uint4*)(Bs + brow*64 + (16*lc ^ ((brow & 1) << 5)));
        }
        #pragma unroll
        for (int mi = 0; mi < 4; mi++){
            int ar0 = wm*64 + mi*16 + lr;
            int ar1 = ar0 + 8;
            uint4 A1 = *(const uint4*)(As + ar0*64 + (16*lc ^ ((ar0 & 1) << 5)));
            uint4 A2 = *(const uint4*)(As + ar1*64 + (16*lc ^ ((ar1 & 1) << 5)));
            #pragma unroll
            for (int ni = 0; ni < 8; ni++){
                mma_fp16(acc[mi][ni], A1.x, A2.x, A1.y, A2.y, bf[ni].x, bf[ni].y);
                mma_fp16(acc[mi][ni], A1.z, A2.z, A1.w, A2.w, bf[ni].z, bf[ni].w);
            }
        }
    }

    int b = m0 >> 16;
    float bv0[8], bv1[8];
    #pragma unroll
    for (int ni = 0; ni < 8; ni++){
        int n = wn*64 + ni*8 + lc*2;
        bv0[ni] = g_bias1[b*128 + n];
        bv1[ni] = g_bias1[b*128 + n + 1];
    }
    #pragma unroll
    for (int mi = 0; mi < 4; mi++){
        int mr = m0 + wm*64 + mi*16 + lr;
        float* dst0 = g_h1 + (size_t)mr*128;
        float* dst1 = g_h1 + (size_t)(mr + 8)*128;
        #pragma unroll
        for (int ni = 0; ni < 8; ni++){
            int n = wn*64 + ni*8 + lc*2;
            *(float2*)(dst0 + n) = make_float2(fmaxf(acc[mi][ni][0] + bv0[ni], 0.f),
                                               fmaxf(acc[mi][ni][1] + bv1[ni], 0.f));
            *(float2*)(dst1 + n) = make_float2(fmaxf(acc[mi][ni][2] + bv0[ni], 0.f),
                                               fmaxf(acc[mi][ni][3] + bv1[ni], 0.f));
        }
    }
}

// ---------------- generic fp16 chain GEMM: M-tile 128, K in {64,128}, N in {64,128} ----------------
// EPI: 0 per-batch bias -> half   1 shared bias -> half
//      2 shared bias + relu -> half
//      3 shared bias + relu + identity(fp32) + NCHW scatter -> fp32 out
template<int K, int N, int EPI>
__global__ __launch_bounds__(128, 2) void hgemm_kernel(
    const __half* __restrict__ A, const __half* __restrict__ Bw,
    const float* __restrict__ bias,
    __half* __restrict__ outh, float* __restrict__ outf,
    const float* __restrict__ identity)
{
    constexpr int NCH = K/32;
    constexpr int NW  = N/2;      // warp n-tile
    constexpr int NI  = NW/8;
    __shared__ __align__(16) char As[128*64];
    __shared__ __align__(16) char Bs[N*64];

    int m0  = blockIdx.x*128;
    int tid = threadIdx.x;
    int wid = tid >> 5, lane = tid & 31;
    int wm = wid & 1, wn = wid >> 1;
    int lr = lane >> 2, lc = lane & 3;

    float acc[4][NI][4];
    #pragma unroll
    for (int mi = 0; mi < 4; mi++)
        #pragma unroll
        for (int ni = 0; ni < NI; ni++)
            #pragma unroll
            for (int r = 0; r < 4; r++) acc[mi][ni][r] = 0.f;

    #pragma unroll
    for (int chunk = 0; chunk < NCH; chunk++){
        if (chunk) __syncthreads();
        #pragma unroll
        for (int p = 0; p < 4; p++){
            int idx = tid + p*128;
            int row = idx >> 2, t = idx & 3;
            uint4 va = *(const uint4*)(A + ((size_t)(m0 + row)*K + chunk*32) + t*8);
            *(uint4*)(As + row*64 + (16*t ^ ((row & 1) << 5))) = va;
        }
        #pragma unroll
        for (int p = 0; p < N/32; p++){
            int idx = tid + p*128;
            int row = idx >> 2, t = idx & 3;
            uint4 vb = *(const uint4*)(Bw + ((size_t)row*K + chunk*32) + t*8);
            *(uint4*)(Bs + row*64 + (16*t ^ ((row & 1) << 5))) = vb;
        }
        __syncthreads();

        uint4 bf[NI];
        #pragma unroll
        for (int ni = 0; ni < NI; ni++){
            int brow = wn*NW + ni*8 + lr;
            bf[ni] = *(const uint4*)(Bs + brow*64 + (16*lc ^ ((brow & 1) << 5)));
        }
        #pragma unroll
        for (int mi = 0; mi < 4; mi++){
            int ar0 = wm*64 + mi*16 + lr;
            int ar1 = ar0 + 8;
            uint4 A1 = *(const uint4*)(As + ar0*64 + (16*lc ^ ((ar0 & 1) << 5)));
            uint4 A2 = *(const uint4*)(As + ar1*64 + (16*lc ^ ((ar1 & 1) << 5)));
            #pragma unroll
            for (int ni = 0; ni < NI; ni++){
                mma_fp16(acc[mi][ni], A1.x, A2.x, A1.y, A2.y, bf[ni].x, bf[ni].y);
                mma_fp16(acc[mi][ni], A1.z, A2.z, A1.w, A2.w, bf[ni].z, bf[ni].w);
            }
        }
    }

    int b = m0 >> 16;
    const float* bp = (EPI == 0) ? (bias + b*N) : bias;
    float bv0[NI], bv1[NI];
    int slot[NI];
    #pragma unroll
    for (int ni = 0; ni < NI; ni++){
        int n = wn*NW + ni*8 + lc*2;
        bv0[ni] = bp[n];
        bv1[ni] = bp[n+1];
        slot[ni] = (n >> 5)*32 + lam32(n & 31);
    }

    #pragma unroll
    for (int mi = 0; mi < 4; mi++){
        int mr = m0 + wm*64 + mi*16 + lr;
        if constexpr (EPI == 3){
            int hw0 = mr & 65535, hw1 = (mr + 8) & 65535;
            const float* id0 = identity + (size_t)mr*128;
            const float* id1 = identity + (size_t)(mr + 8)*128;
            #pragma unroll
            for (int ni = 0; ni < NI; ni++){
                int n = wn*NW + ni*8 + lc*2;
                float* o0 = outf + ((size_t)(b*128 + n))*65536;
                float* o1 = outf + ((size_t)(b*128 + n + 1))*65536;
                o0[hw0] = fmaxf(acc[mi][ni][0] + bv0[ni], 0.f) + id0[n];
                o1[hw0] = fmaxf(acc[mi][ni][1] + bv1[ni], 0.f) + id0[n+1];
                o0[hw1] = fmaxf(acc[mi][ni][2] + bv0[ni], 0.f) + id1[n];
                o1[hw1] = fmaxf(acc[mi][ni][3] + bv1[ni], 0.f) + id1[n+1];
            }
        } else {
            __half* dst0 = outh + (size_t)mr*N;
            __half* dst1 = outh + (size_t)(mr + 8)*N;
            #pragma unroll
            for (int ni = 0; ni < NI; ni++){
                float v0 = acc[mi][ni][0] + bv0[ni];
                float v1 = acc[mi][ni][1] + bv1[ni];
                float v2 = acc[mi][ni][2] + bv0[ni];
                float v3 = acc[mi][ni][3] + bv1[ni];
                if (EPI == 2){
                    v0 = fmaxf(v0,0.f); v1 = fmaxf(v1,0.f);
                    v2 = fmaxf(v2,0.f); v3 = fmaxf(v3,0.f);
                }
                *(__half2*)(dst0 + slot[ni]) = __floats2half2_rn(v0, v1);
                *(__half2*)(dst1 + slot[ni]) = __floats2half2_rn(v2, v3);
            }
        }
    }
}

// ---------------- deterministic layernorm ----------------
__global__ void ln_part(){
    int b = blockIdx.y, blk = blockIdx.x, tid = threadIdx.x;
    const float4* p = (const float4*)(g_h1 + (size_t)b*8388608 + (size_t)blk*16384);
    float s = 0.f, s2 = 0.f;
    for (int i = tid; i < 4096; i += 256){
        float4 v = p[i];
        s  += v.x + v.y + v.z + v.w;
        s2 += v.x*v.x + v.y*v.y + v.z*v.z + v.w*v.w;
    }
    __shared__ float sh[256], sh2[256];
    sh[tid] = s; sh2[tid] = s2; __syncthreads();
    for (int st = 128; st > 0; st >>= 1){
        if (tid < st){ sh[tid] += sh[tid+st]; sh2[tid] += sh2[tid+st]; }
        __syncthreads();
    }
    if (tid == 0){
        g_part[(b*512 + blk)*2    ] = sh[0];
        g_part[(b*512 + blk)*2 + 1] = sh2[0];
    }
}

__global__ void ln_finish(){
    int b = blockIdx.x, tid = threadIdx.x;
    float s = 0.f, s2 = 0.f;
    for (int i = tid; i < 512; i += 256){
        s  += g_part[(b*512 + i)*2];
        s2 += g_part[(b*512 + i)*2 + 1];
    }
    __shared__ float sh[256], sh2[256];
    sh[tid] = s; sh2[tid] = s2; __syncthreads();
    for (int st = 128; st > 0; st >>= 1){
        if (tid < st){ sh[tid] += sh[tid+st]; sh2[tid] += sh2[tid+st]; }
        __syncthreads();
    }
    if (tid == 0){
        const float invN = 1.f / 8388608.f;
        float mu  = sh[0] * invN;
        float var = sh2[0] * invN - mu*mu;
        g_stats[b*2]     = mu;
        g_stats[b*2 + 1] = rsqrtf(var + 1e-5f);
    }
}

// LN apply -> half interleaved
__global__ void ln_apply(const float* __restrict__ lnw, const float* __restrict__ lnb){
    size_t e = ((size_t)blockIdx.x*256 + threadIdx.x)*4;
    int b = (int)(e >> 23);
    float mu = g_stats[b*2], rs = g_stats[b*2 + 1];
    size_t li = e & 8388607u;
    int m = (int)(e >> 7);
    int c = (int)(e & 127);
    float4 h = *(const float4*)&g_h1[e];
    float4 w = *(const float4*)&lnw[li];
    float4 cc = *(const float4*)&lnb[li];
    float o0 = (h.x - mu)*rs*w.x + cc.x;
    float o1 = (h.y - mu)*rs*w.y + cc.y;
    float o2 = (h.z - mu)*rs*w.z + cc.z;
    float o3 = (h.w - mu)*rs*w.w + cc.w;
    __half* dst = g_lnh + (size_t)m*128;
    int s0 = (c >> 5)*32 + lam32(c & 31);
    int s1 = ((c+2) >> 5)*32 + lam32((c+2) & 31);
    *(__half2*)(dst + s0) = __floats2half2_rn(o0, o1);
    *(__half2*)(dst + s1) = __floats2half2_rn(o2, o3);
}

// ---------------- launch ----------------
extern "C" void kernel_launch(void* const* d_in, const int* in_sizes, int n_in,
                              void* d_out, int out_size){
    const float* x      = (const float*)d_in[0];
    const float* y      = (const float*)d_in[1];
    const float* s      = (const float*)d_in[2];
    const float* conv_w = (const float*)d_in[4];
    const float* conv_b = (const float*)d_in[5];
    const float* mlp1_w = (const float*)d_in[6];
    const float* mlp1_b = (const float*)d_in[7];
    const float* ln_w   = (const float*)d_in[8];
    const float* ln_b   = (const float*)d_in[9];
    const float* m3_w1  = (const float*)d_in[10];
    const float* m3_b2  = (const float*)d_in[13];
    const float* m3_w2  = (const float*)d_in[12];
    const float* m3_w3  = (const float*)d_in[14];
    const float* m3_b3  = (const float*)d_in[15];
    const float* m4_w1  = (const float*)d_in[16];
    const float* m4_w2  = (const float*)d_in[18];
    const float* m4_b2  = (const float*)d_in[19];
    const float* m4_w3  = (const float*)d_in[20];
    const float* m4_b3  = (const float*)d_in[21];
    const float* m3_b1  = (const float*)d_in[11];
    const float* m4_b1  = (const float*)d_in[17];
    float* out = (float*)d_out;

    void *ph1, *plnh, *pt1, *pt2, *pt3, *pb3, *pb4;
    void *pw3a, *pw3b, *pw3c, *pw4a, *pw4b, *pw4c;
    cudaGetSymbolAddress(&ph1, g_h1);
    cudaGetSymbolAddress(&plnh, g_lnh);
    cudaGetSymbolAddress(&pt1, g_t1h);
    cudaGetSymbolAddress(&pt2, g_t2h);
    cudaGetSymbolAddress(&pt3, g_t3h);
    cudaGetSymbolAddress(&pb3, g_bias3);
    cudaGetSymbolAddress(&pb4, g_bias4);
    cudaGetSymbolAddress(&pw3a, g_w3a);
    cudaGetSymbolAddress(&pw3b, g_w3b);
    cudaGetSymbolAddress(&pw3c, g_w3c);
    cudaGetSymbolAddress(&pw4a, g_w4a);
    cudaGetSymbolAddress(&pw4b, g_w4b);
    cudaGetSymbolAddress(&pw4c, g_w4c);

    prep_w9h<<<1152, 256>>>(conv_w);
    prep_w1h<<<128, 256>>>(mlp1_w);
    prep_wh<<<32, 256>>>(m3_w1, (__half*)pw3a, 128, 64);
    prep_wh<<<16, 256>>>(m3_w2, (__half*)pw3b, 64, 64);
    prep_wh<<<32, 256>>>(m3_w3, (__half*)pw3c, 64, 128);
    prep_wh<<<32, 256>>>(m4_w1, (__half*)pw4a, 128, 64);
    prep_wh<<<16, 256>>>(m4_w2, (__half*)pw4b, 64, 64);
    prep_wh<<<32, 256>>>(m4_w3, (__half*)pw4c, 64, 128);
    prep_bias<<<1, 256>>>(s, mlp1_w, mlp1_b, m3_w1, m3_b1, m4_w1, m4_b1);
    upsample_kernel<<<131072, 256>>>(x);
    xup_kernel<<<dim3(8, 8, 2048), dim3(32, 8)>>>();
    ycopy_kernel<<<dim3(8, 4, 2048), dim3(32, 8)>>>(y);
    conv_mma_kernel<<<4096, 128>>>(conv_b);
    mlp1_mma_kernel<<<4096, 128>>>();

    // layernorm
    ln_part<<<dim3(512, 8), 256>>>();
    ln_finish<<<8, 256>>>();
    ln_apply<<<65536, 256>>>(ln_w, ln_b);

    // mlp3 (fp16)
    hgemm_kernel<128,64,0><<<4096, 128>>>((const __half*)plnh, (const __half*)pw3a,
                                          (const float*)pb3, (__half*)pt1, nullptr, nullptr);
    hgemm_kernel<64,64,1><<<4096, 128>>>((const __half*)pt1, (const __half*)pw3b,
                                         m3_b2, (__half*)pt2, nullptr, nullptr);
    hgemm_kernel<64,128,2><<<4096, 128>>>((const __half*)pt2, (const __half*)pw3c,
                                          m3_b3, (__half*)pt3, nullptr, nullptr);
    // mlp4 (+ identity add + NCHW scatter)
    hgemm_kernel<128,64,0><<<4096, 128>>>((const __half*)pt3, (const __half*)pw4a,
                                          (const float*)pb4, (__half*)pt1, nullptr, nullptr);
    hgemm_kernel<64,64,1><<<4096, 128>>>((const __half*)pt1, (const __half*)pw4b,
                                         m4_b2, (__half*)pt2, nullptr, nullptr);
    hgemm_kernel<64,128,3><<<4096, 128>>>((const __half*)pt2, (const __half*)pw4c,
                                          m4_b3, nullptr, out, (const float*)ph1);
}

// round 8
// speedup vs baseline: 3.8592x; 1.0581x over previous
#include <cuda_runtime.h>
#include <cuda_fp16.h>
#include <math.h>
#include <stdint.h>

#define BATCH 8
#define UPC   256
#define HH    256
#define WWD   256
#define HWN   65536
#define MTOT  (BATCH*HWN)   // 524288

// ---------------- scratch (static device globals; allocation-free) ----------------
__device__ __half g_xuPh[(size_t)BATCH*HWN*UPC];   // [b][h][c8][w][32] pair-interleaved half
__device__ __half g_fh  [(size_t)MTOT*256];        // concat(xc,y) NHWC, pair-interleaved half
__device__ float  g_h1 [(size_t)MTOT*128];         // mlp1 out fp32 (LN stats + identity)
__device__ __half g_lnh[(size_t)MTOT*128];         // layernorm out, interleaved half
__device__ __half g_t1h[(size_t)MTOT*64];
__device__ __half g_t2h[(size_t)MTOT*64];
__device__ __half g_t3h[(size_t)MTOT*128];
__device__ __half g_w9ph[9*8*128*32];              // conv weights [off][c8][co][32] interleaved
__device__ __half g_w1h [128*256];                 // mlp1 W^T [n][k-interleaved]
__device__ __half g_w3a[64*128], g_w3b[64*64], g_w3c[128*64];
__device__ __half g_w4a[64*128], g_w4b[64*64], g_w4c[128*64];
__device__ float  g_bias1[BATCH*128];
__device__ float  g_bias3[BATCH*64];
__device__ float  g_bias4[BATCH*64];
__device__ float  g_part[BATCH*512*2];
__device__ float  g_stats[BATCH*2];

// channel c (0..31) -> half slot within 32-half chunk (pair-interleaved)
__device__ __forceinline__ int lam32(int c){
    int g  = c >> 4;
    int kp = (c & 15) >> 1;
    int o  = c & 1;
    return 8*(kp & 3) + 4*g + 2*(kp >> 2) + o;
}

__device__ __forceinline__ void mma_fp16(float c[4],
        uint32_t a0, uint32_t a1, uint32_t a2, uint32_t a3,
        uint32_t b0, uint32_t b1){
    asm volatile(
        "mma.sync.aligned.m16n8k16.row.col.f32.f16.f16.f32 "
        "{%0,%1,%2,%3}, {%4,%5,%6,%7}, {%8,%9}, {%0,%1,%2,%3};"
        : "+f"(c[0]), "+f"(c[1]), "+f"(c[2]), "+f"(c[3])
        : "r"(a0), "r"(a1), "r"(a2), "r"(a3), "r"(b0), "r"(b1));
}

__device__ __forceinline__ void cp16(uint32_t dst, const void* src, int bytes){
    asm volatile("cp.async.cg.shared.global [%0], [%1], 16, %2;"
                 :: "r"(dst), "l"(src), "r"(bytes));
}
__device__ __forceinline__ void cp_commit(){
    asm volatile("cp.async.commit_group;");
}
__device__ __forceinline__ void cp_wait1(){
    asm volatile("cp.async.wait_group 1;");
}
__device__ __forceinline__ void cp_wait0(){
    asm volatile("cp.async.wait_group 0;");
}

// ---------------- prep kernels ----------------
__global__ void prep_w9h(const float* __restrict__ cw){
    int i = blockIdx.x*256 + threadIdx.x;
    if (i < 9*8*128*32){
        int c   = i & 31;
        int co  = (i >> 5) & 127;
        int c8  = (i >> 12) & 7;
        int off = i >> 15;
        int ci  = c8*32 + c;
        g_w9ph[(((off*8 + c8)*128 + co)*32) + lam32(c)] =
            __float2half_rn(cw[(co*256 + ci)*9 + off]);
    }
}

__global__ void prep_w1h(const float* __restrict__ w1){
    int i = blockIdx.x*256 + threadIdx.x;
    if (i < 128*256){
        int k = i & 255, n = i >> 8;
        g_w1h[n*256 + (k>>5)*32 + lam32(k & 31)] = __float2half_rn(w1[k*128 + n]);
    }
}

__global__ void prep_wh(const float* __restrict__ w, __half* __restrict__ o,
                        int K, int N){
    int i = blockIdx.x*256 + threadIdx.x;
    if (i < K*N){
        int k = i % K, n = i / K;
        o[n*K + (k>>5)*32 + lam32(k & 31)] = __float2half_rn(w[k*N + n]);
    }
}

__global__ void prep_bias(const float* __restrict__ s,
                          const float* __restrict__ m1w, const float* __restrict__ m1b,
                          const float* __restrict__ w3,  const float* __restrict__ b3,
                          const float* __restrict__ w4,  const float* __restrict__ b4){
    int t = threadIdx.x;
    for (int b = 0; b < BATCH; b++){
        float sb = s[b];
        if (t < 128) g_bias1[b*128+t] = m1b[t] + sb*m1w[256*128 + t];
        if (t < 64){
            g_bias3[b*64+t] = b3[t] + sb*w3[128*64 + t];
            g_bias4[b*64+t] = b4[t] + sb*w4[128*64 + t];
        }
    }
}

// ---------------- fused bicubic 2x upsample -> interleaved half (g_xuPh) ----------------
// block: (kh, c8, b); computes output rows 2kh, 2kh+1 for 32 channels, all 256 w.
__global__ __launch_bounds__(256) void upsample_fused_kernel(const float* __restrict__ x){
    __shared__ __half sm[2][256][32];
    int kh = blockIdx.x, c8 = blockIdx.y, b = blockIdx.z;
    int tid = threadIdx.x;
    int lane = tid & 31, warp = tid >> 5;

    int rr[5];
    #pragma unroll
    for (int i = 0; i < 5; i++){
        int r = kh - 2 + i; rr[i] = min(max(r,0),127);
    }
    const float we0=-0.03515625f, we1=0.26171875f, we2=0.87890625f, we3=-0.10546875f;
    const float wo0=-0.10546875f, wo1=0.87890625f, wo2=0.26171875f, wo3=-0.03515625f;

    #pragma unroll
    for (int q = 0; q < 4; q++){
        int cg = warp*4 + q;                     // channel within group
        int c  = c8*32 + cg;
        const float* xp = x + ((size_t)(b*256 + c))*16384;
        int slot = lam32(cg);
        #pragma unroll
        for (int j = 0; j < 4; j++){
            int kw = lane + 32*j;
            int cc[5];
            #pragma unroll
            for (int i = 0; i < 5; i++){
                int cw_ = kw - 2 + i; cc[i] = min(max(cw_,0),127);
            }
            float he[5], ho[5];
            #pragma unroll
            for (int i = 0; i < 5; i++){
                const float* row = xp + rr[i]*128;
                float v0=row[cc[0]], v1=row[cc[1]], v2=row[cc[2]], v3=row[cc[3]], v4=row[cc[4]];
                he[i] = we0*v0 + we1*v1 + we2*v2 + we3*v3;
                ho[i] = wo0*v1 + wo1*v2 + wo2*v3 + wo3*v4;
            }
            float o00 = we0*he[0]+we1*he[1]+we2*he[2]+we3*he[3];
            float o01 = we0*ho[0]+we1*ho[1]+we2*ho[2]+we3*ho[3];
            float o10 = wo0*he[1]+wo1*he[2]+wo2*he[3]+wo3*he[4];
            float o11 = wo0*ho[1]+wo1*ho[2]+wo2*ho[3]+wo3*ho[4];
            sm[0][2*kw  ][slot] = __float2half_rn(o00);
            sm[0][2*kw+1][slot] = __float2half_rn(o01);
            sm[1][2*kw  ][slot] = __float2half_rn(o10);
            sm[1][2*kw+1][slot] = __float2half_rn(o11);
        }
    }
    __syncthreads();

    __half* out0 = g_xuPh + ((size_t)((b*256 + 2*kh    )*8 + c8))*8192;
    __half* out1 = g_xuPh + ((size_t)((b*256 + 2*kh + 1)*8 + c8))*8192;
    const uint4* s0 = (const uint4*)&sm[0][0][0];
    const uint4* s1 = (const uint4*)&sm[1][0][0];
    #pragma unroll
    for (int p = 0; p < 4; p++){
        ((uint4*)out0)[p*256 + tid] = s0[p*256 + tid];
        ((uint4*)out1)[p*256 + tid] = s1[p*256 + tid];
    }
}

// ---------------- y NCHW -> f half (channels 128..255, interleaved slots) ----------------
__global__ void ycopy_kernel(const float* __restrict__ y){
    __shared__ float tile[32][33];
    int w0 = blockIdx.x*32, cb = blockIdx.y;
    int bh = blockIdx.z;
    int b = bh >> 8, h = bh & 255;
    int tx = threadIdx.x, ty = threadIdx.y;
    int c0 = cb*32;
    #pragma unroll
    for (int k = 0; k < 4; k++){
        int c = c0 + ty + k*8;
        tile[ty + k*8][tx] = y[(((size_t)b*128 + c)*256 + h)*256 + w0 + tx];
    }
    __syncthreads();
    int slot = (4 + cb)*32 + lam32(tx);
    #pragma unroll
    for (int k = 0; k < 4; k++){
        int w = w0 + ty + k*8;
        g_fh[(((size_t)b*256 + h)*256 + w)*256 + slot] = __float2half_rn(tile[tx][ty + k*8]);
    }
}

// ---------------- conv 3x3 via fp16 mma, cp.async double-buffered ----------------
// dynamic SMEM layout: A0 @0 (8320B), A1 @8320, B0 @16640 (24576B), B1 @41216; total 65792
#define CONV_SMEM 65792

__global__ __launch_bounds__(128, 2) void conv_mma_kernel(const float* __restrict__ convb){
    extern __shared__ char dsm[];
    char* const Ab[2] = {dsm, dsm + 8320};
    char* const Bb[2] = {dsm + 16640, dsm + 41216};
    uint32_t Au[2], Bu[2];
    Au[0] = (uint32_t)__cvta_generic_to_shared(Ab[0]);
    Au[1] = (uint32_t)__cvta_generic_to_shared(Ab[1]);
    Bu[0] = (uint32_t)__cvta_generic_to_shared(Bb[0]);
    Bu[1] = (uint32_t)__cvta_generic_to_shared(Bb[1]);

    int bx = blockIdx.x;
    int w0 = (bx & 1)*128;
    int h  = (bx >> 1) & 255;
    int b  = bx >> 9;
    int tid = threadIdx.x;
    int wid = tid >> 5, lane = tid & 31;
    int wm = wid & 1, wn = wid >> 1;
    int lr = lane >> 2, lc = lane & 3;

    int hhs[3], off3s[3], nh = 0;
    #pragma unroll
    for (int dh = -1; dh <= 1; dh++){
        int hh = h + dh;
        if (hh >= 0 && hh < HH){ hhs[nh] = hh; off3s[nh] = (dh+1)*3; nh++; }
    }
    int nch = nh*8;

    float acc[4][8][4];
    #pragma unroll
    for (int mi = 0; mi < 4; mi++)
        #pragma unroll
        for (int ni = 0; ni < 8; ni++)
            #pragma unroll
            for (int r = 0; r < 4; r++) acc[mi][ni][r] = 0.f;

    // fill chunk i into buffer s
    auto fill = [&](int i, int s){
        int ih = i >> 3, c8 = i & 7;
        const __half* aplane = g_xuPh + ((size_t)((b*256 + hhs[ih])*8 + c8))*8192;
        #pragma unroll
        for (int p = 0; p < 5; p++){
            int idx = tid + p*128;
            if (idx < 520){
                int row = idx >> 2, t = idx & 3;
                int w_in = w0 - 1 + row;
                int ok = (w_in >= 0 && w_in < WWD) ? 16 : 0;
                int wc = min(max(w_in, 0), WWD-1);
                cp16(Au[s] + row*64 + (16*t ^ ((row & 1) << 5)),
                     aplane + wc*32 + t*8, ok);
            }
        }
        const __half* wb = g_w9ph + ((size_t)(off3s[ih]*8 + c8))*128*32;
        #pragma unroll
        for (int p = 0; p < 12; p++){
            int idx = tid + p*128;
            int row = idx >> 2, t = idx & 3;
            int dwi = row >> 7, co = row & 127;
            cp16(Bu[s] + row*64 + (16*t ^ ((row & 1) << 5)),
                 wb + ((size_t)dwi*8*128*32) + co*32 + t*8, 16);
        }
    };

    fill(0, 0);
    cp_commit();

    for (int i = 0; i < nch; i++){
        int s = i & 1;
        if (i + 1 < nch){ fill(i+1, s^1); cp_commit(); cp_wait1(); }
        else cp_wait0();
        __syncthreads();

        char* As = Ab[s];
        char* Bs = Bb[s];
        #pragma unroll
        for (int dwi = 0; dwi < 3; dwi++){
            uint4 bf[8];
            #pragma unroll
            for (int ni = 0; ni < 8; ni++){
                int brow = dwi*128 + wn*64 + ni*8 + lr;
                bf[ni] = *(const uint4*)(Bs + brow*64 + (16*lc ^ ((brow & 1) << 5)));
            }
            #pragma unroll
            for (int mi = 0; mi < 4; mi++){
                int ar0 = wm*64 + mi*16 + lr + dwi;
                int ar1 = ar0 + 8;
                uint4 A1 = *(const uint4*)(As + ar0*64 + (16*lc ^ ((ar0 & 1) << 5)));
                uint4 A2 = *(const uint4*)(As + ar1*64 + (16*lc ^ ((ar1 & 1) << 5)));
                #pragma unroll
                for (int ni = 0; ni < 8; ni++){
                    mma_fp16(acc[mi][ni], A1.x, A2.x, A1.y, A2.y, bf[ni].x, bf[ni].y);
                    mma_fp16(acc[mi][ni], A1.z, A2.z, A1.w, A2.w, bf[ni].z, bf[ni].w);
                }
            }
        }
        __syncthreads();
    }

    float bv0[8], bv1[8];
    int slot[8];
    #pragma unroll
    for (int ni = 0; ni < 8; ni++){
        int n = wn*64 + ni*8 + lc*2;
        bv0[ni] = convb[n];
        bv1[ni] = convb[n+1];
        slot[ni] = (n >> 5)*32 + lam32(n & 31);
    }
    #pragma unroll
    for (int mi = 0; mi < 4; mi++){
        int m0 = wm*64 + mi*16 + lr;
        __half* dst0 = g_fh + (((size_t)b*256 + h)*256 + w0 + m0    )*256;
        __half* dst1 = g_fh + (((size_t)b*256 + h)*256 + w0 + m0 + 8)*256;
        #pragma unroll
        for (int ni = 0; ni < 8; ni++){
            *(__half2*)(dst0 + slot[ni]) =
                __floats2half2_rn(acc[mi][ni][0] + bv0[ni], acc[mi][ni][1] + bv1[ni]);
            *(__half2*)(dst1 + slot[ni]) =
                __floats2half2_rn(acc[mi][ni][2] + bv0[ni], acc[mi][ni][3] + bv1[ni]);
        }
    }
}

// ---------------- mlp1 via fp16 mma, cp.async double-buffered ----------------
__global__ __launch_bounds__(128, 2) void mlp1_mma_kernel(){
    __shared__ __align__(16) char As[2][8192];
    __shared__ __align__(16) char Bs[2][8192];
    uint32_t AsU[2], BsU[2];
    AsU[0] = (uint32_t)__cvta_generic_to_shared(As[0]);
    AsU[1] = (uint32_t)__cvta_generic_to_shared(As[1]);
    BsU[0] = (uint32_t)__cvta_generic_to_shared(Bs[0]);
    BsU[1] = (uint32_t)__cvta_generic_to_shared(Bs[1]);

    int m0  = blockIdx.x*128;
    int tid = threadIdx.x;
    int wid = tid >> 5, lane = tid & 31;
    int wm = wid & 1, wn = wid >> 1;
    int lr = lane >> 2, lc = lane & 3;

    float acc[4][8][4];
    #pragma unroll
    for (int mi = 0; mi < 4; mi++)
        #pragma unroll
        for (int ni = 0; ni < 8; ni++)
            #pragma unroll
            for (int r = 0; r < 4; r++) acc[mi][ni][r] = 0.f;

    auto fill = [&](int chunk, int s){
        #pragma unroll
        for (int p = 0; p < 4; p++){
            int idx = tid + p*128;
            int row = idx >> 2, t = idx & 3;
            uint32_t sw = 16*t ^ ((row & 1) << 5);
            cp16(AsU[s] + row*64 + sw,
                 g_fh + ((size_t)(m0 + row)*256 + chunk*32) + t*8, 16);
            cp16(BsU[s] + row*64 + sw,
                 g_w1h + (row*256 + chunk*32) + t*8, 16);
        }
    };

    fill(0, 0);
    cp_commit();

    for (int chunk = 0; chunk < 8; chunk++){
        int s = chunk & 1;
        if (chunk + 1 < 8){ fill(chunk+1, s^1); cp_commit(); cp_wait1(); }
        else cp_wait0();
        __syncthreads();

        uint4 bf[8];
        #pragma unroll
        for (int ni = 0; ni < 8; ni++){
            int brow = wn*64 + ni*8 + lr;
            bf[ni] = *(const uint4*)(Bs[s] + brow*64 + (16*lc ^ ((brow & 1) << 5)));
        }
        #pragma unroll
        for (int mi = 0; mi < 4; mi++){
            int ar0 = wm*64 + mi*16 + lr;
            int ar1 = ar0 + 8;
            uint4 A1 = *(const uint4*)(As[s] + ar0*64 + (16*lc ^ ((ar0 & 1) << 5)));
            uint4 A2 = *(const uint4*)(As[s] + ar1*64 + (16*lc ^ ((ar1 & 1) << 5)));
            #pragma unroll
            for (int ni = 0; ni < 8; ni++){
                mma_fp16(acc[mi][ni], A1.x, A2.x, A1.y, A2.y, bf[ni].x, bf[ni].y);
                mma_fp16(acc[mi][ni], A1.z, A2.z, A1.w, A2.w, bf[ni].z, bf[ni].w);
            }
        }
        __syncthreads();
    }

    int b = m0 >> 16;
    float bv0[8], bv1[8];
    #pragma unroll
    for (int ni = 0; ni < 8; ni++){
        int n = wn*64 + ni*8 + lc*2;
        bv0[ni] = g_bias1[b*128 + n];
        bv1[ni] = g_bias1[b*128 + n + 1];
    }
    #pragma unroll
    for (int mi = 0; mi < 4; mi++){
        int mr = m0 + wm*64 + mi*16 + lr;
        float* dst0 = g_h1 + (size_t)mr*128;
        float* dst1 = g_h1 + (size_t)(mr + 8)*128;
        #pragma unroll
        for (int ni = 0; ni < 8; ni++){
            int n = wn*64 + ni*8 + lc*2;
            *(float2*)(dst0 + n) = make_float2(fmaxf(acc[mi][ni][0] + bv0[ni], 0.f),
                                               fmaxf(acc[mi][ni][1] + bv1[ni], 0.f));
            *(float2*)(dst1 + n) = make_float2(fmaxf(acc[mi][ni][2] + bv0[ni], 0.f),
                                               fmaxf(acc[mi][ni][3] + bv1[ni], 0.f));
        }
    }
}

// ---------------- generic fp16 chain GEMM (unchanged from R7) ----------------
template<int K, int N, int EPI>
__global__ __launch_bounds__(128, 2) void hgemm_kernel(
    const __half* __restrict__ A, const __half* __restrict__ Bw,
    const float* __restrict__ bias,
    __half* __restrict__ outh, float* __restrict__ outf,
    const float* __restrict__ identity)
{
    constexpr int NCH = K/32;
    constexpr int NW  = N/2;
    constexpr int NI  = NW/8;
    __shared__ __align__(16) char As[128*64];
    __shared__ __align__(16) char Bs[N*64];

    int m0  = blockIdx.x*128;
    int tid = threadIdx.x;
    int wid = tid >> 5, lane = tid & 31;
    int wm = wid & 1, wn = wid >> 1;
    int lr = lane >> 2, lc = lane & 3;

    float acc[4][NI][4];
    #pragma unroll
    for (int mi = 0; mi < 4; mi++)
        #pragma unroll
        for (int ni = 0; ni < NI; ni++)
            #pragma unroll
            for (int r = 0; r < 4; r++) acc[mi][ni][r] = 0.f;

    #pragma unroll
    for (int chunk = 0; chunk < NCH; chunk++){
        if (chunk) __syncthreads();
        #pragma unroll
        for (int p = 0; p < 4; p++){
            int idx = tid + p*128;
            int row = idx >> 2, t = idx & 3;
            uint4 va = *(const uint4*)(A + ((size_t)(m0 + row)*K + chunk*32) + t*8);
            *(uint4*)(As + row*64 + (16*t ^ ((row & 1) << 5))) = va;
        }
        #pragma unroll
        for (int p = 0; p < N/32; p++){
            int idx = tid + p*128;
            int row = idx >> 2, t = idx & 3;
            uint4 vb = *(const uint4*)(Bw + ((size_t)row*K + chunk*32) + t*8);
            *(uint4*)(Bs + row*64 + (16*t ^ ((row & 1) << 5))) = vb;
        }
        __syncthreads();

        uint4 bf[NI];
        #pragma unroll
        for (int ni = 0; ni < NI; ni++){
            int brow = wn*NW + ni*8 + lr;
            bf[ni] = *(const uint4*)(Bs + brow*64 + (16*lc ^ ((brow & 1) << 5)));
        }
        #pragma unroll
        for (int mi = 0; mi < 4; mi++){
            int ar0 = wm*64 + mi*16 + lr;
            int ar1 = ar0 + 8;
            uint4 A1 = *(const uint4*)(As + ar0*64 + (16*lc ^ ((ar0 & 1) << 5)));
            uint4 A2 = *(const uint4*)(As + ar1*64 + (16*lc ^ ((ar1 & 1) << 5)));
            #pragma unroll
            for (int ni = 0; ni < NI; ni++){
                mma_fp16(acc[mi][ni], A1.x, A2.x, A1.y, A2.y, bf[ni].x, bf[ni].y);
                mma_fp16(acc[mi][ni], A1.z, A2.z, A1.w, A2.w, bf[ni].z, bf[ni].w);
            }
        }
    }

    int b = m0 >> 16;
    const float* bp = (EPI == 0) ? (bias + b*N) : bias;
    float bv0[NI], bv1[NI];
    int slot[NI];
    #pragma unroll
    for (int ni = 0; ni < NI; ni++){
        int n = wn*NW + ni*8 + lc*2;
        bv0[ni] = bp[n];
        bv1[ni] = bp[n+1];
        slot[ni] = (n >> 5)*32 + lam32(n & 31);
    }

    #pragma unroll
    for (int mi = 0; mi < 4; mi++){
        int mr = m0 + wm*64 + mi*16 + lr;
        if constexpr (EPI == 3){
            int hw0 = mr & 65535, hw1 = (mr + 8) & 65535;
            const float* id0 = identity + (size_t)mr*128;
            const float* id1 = identity + (size_t)(mr + 8)*128;
            #pragma unroll
            for (int ni = 0; ni < NI; ni++){
                int n = wn*NW + ni*8 + lc*2;
                float* o0 = outf + ((size_t)(b*128 + n))*65536;
                float* o1 = outf + ((size_t)(b*128 + n + 1))*65536;
                o0[hw0] = fmaxf(acc[mi][ni][0] + bv0[ni], 0.f) + id0[n];
                o1[hw0] = fmaxf(acc[mi][ni][1] + bv1[ni], 0.f) + id0[n+1];
                o0[hw1] = fmaxf(acc[mi][ni][2] + bv0[ni], 0.f) + id1[n];
                o1[hw1] = fmaxf(acc[mi][ni][3] + bv1[ni], 0.f) + id1[n+1];
            }
        } else {
            __half* dst0 = outh + (size_t)mr*N;
            __half* dst1 = outh + (size_t)(mr + 8)*N;
            #pragma unroll
            for (int ni = 0; ni < NI; ni++){
                float v0 = acc[mi][ni][0] + bv0[ni];
                float v1 = acc[mi][ni][1] + bv1[ni];
                float v2 = acc[mi][ni][2] + bv0[ni];
                float v3 = acc[mi][ni][3] + bv1[ni];
                if (EPI == 2){
                    v0 = fmaxf(v0,0.f); v1 = fmaxf(v1,0.f);
                    v2 = fmaxf(v2,0.f); v3 = fmaxf(v3,0.f);
                }
                *(__half2*)(dst0 + slot[ni]) = __floats2half2_rn(v0, v1);
                *(__half2*)(dst1 + slot[ni]) = __floats2half2_rn(v2, v3);
            }
        }
    }
}

// ---------------- deterministic layernorm ----------------
__global__ void ln_part(){
    int b = blockIdx.y, blk = blockIdx.x, tid = threadIdx.x;
    const float4* p = (const float4*)(g_h1 + (size_t)b*8388608 + (size_t)blk*16384);
    float s = 0.f, s2 = 0.f;
    for (int i = tid; i < 4096; i += 256){
        float4 v = p[i];
        s  += v.x + v.y + v.z + v.w;
        s2 += v.x*v.x + v.y*v.y + v.z*v.z + v.w*v.w;
    }
    __shared__ float sh[256], sh2[256];
    sh[tid] = s; sh2[tid] = s2; __syncthreads();
    for (int st = 128; st > 0; st >>= 1){
        if (tid < st){ sh[tid] += sh[tid+st]; sh2[tid] += sh2[tid+st]; }
        __syncthreads();
    }
    if (tid == 0){
        g_part[(b*512 + blk)*2    ] = sh[0];
        g_part[(b*512 + blk)*2 + 1] = sh2[0];
    }
}

__global__ void ln_finish(){
    int b = blockIdx.x, tid = threadIdx.x;
    float s = 0.f, s2 = 0.f;
    for (int i = tid; i < 512; i += 256){
        s  += g_part[(b*512 + i)*2];
        s2 += g_part[(b*512 + i)*2 + 1];
    }
    __shared__ float sh[256], sh2[256];
    sh[tid] = s; sh2[tid] = s2; __syncthreads();
    for (int st = 128; st > 0; st >>= 1){
        if (tid < st){ sh[tid] += sh[tid+st]; sh2[tid] += sh2[tid+st]; }
        __syncthreads();
    }
    if (tid == 0){
        const float invN = 1.f / 8388608.f;
        float mu  = sh[0] * invN;
        float var = sh2[0] * invN - mu*mu;
        g_stats[b*2]     = mu;
        g_stats[b*2 + 1] = rsqrtf(var + 1e-5f);
    }
}

__global__ void ln_apply(const float* __restrict__ lnw, const float* __restrict__ lnb){
    size_t e = ((size_t)blockIdx.x*256 + threadIdx.x)*4;
    int b = (int)(e >> 23);
    float mu = g_stats[b*2], rs = g_stats[b*2 + 1];
    size_t li = e & 8388607u;
    int m = (int)(e >> 7);
    int c = (int)(e & 127);
    float4 h = *(const float4*)&g_h1[e];
    float4 w = *(const float4*)&lnw[li];
    float4 cc = *(const float4*)&lnb[li];
    float o0 = (h.x - mu)*rs*w.x + cc.x;
    float o1 = (h.y - mu)*rs*w.y + cc.y;
    float o2 = (h.z - mu)*rs*w.z + cc.z;
    float o3 = (h.w - mu)*rs*w.w + cc.w;
    __half* dst = g_lnh + (size_t)m*128;
    int s0 = (c >> 5)*32 + lam32(c & 31);
    int s1 = ((c+2) >> 5)*32 + lam32((c+2) & 31);
    *(__half2*)(dst + s0) = __floats2half2_rn(o0, o1);
    *(__half2*)(dst + s1) = __floats2half2_rn(o2, o3);
}

// ---------------- launch ----------------
extern "C" void kernel_launch(void* const* d_in, const int* in_sizes, int n_in,
                              void* d_out, int out_size){
    const float* x      = (const float*)d_in[0];
    const float* y      = (const float*)d_in[1];
    const float* s      = (const float*)d_in[2];
    const float* conv_w = (const float*)d_in[4];
    const float* conv_b = (const float*)d_in[5];
    const float* mlp1_w = (const float*)d_in[6];
    const float* mlp1_b = (const float*)d_in[7];
    const float* ln_w   = (const float*)d_in[8];
    const float* ln_b   = (const float*)d_in[9];
    const float* m3_w1  = (const float*)d_in[10];
    const float* m3_b1  = (const float*)d_in[11];
    const float* m3_w2  = (const float*)d_in[12];
    const float* m3_b2  = (const float*)d_in[13];
    const float* m3_w3  = (const float*)d_in[14];
    const float* m3_b3  = (const float*)d_in[15];
    const float* m4_w1  = (const float*)d_in[16];
    const float* m4_b1  = (const float*)d_in[17];
    const float* m4_w2  = (const float*)d_in[18];
    const float* m4_b2  = (const float*)d_in[19];
    const float* m4_w3  = (const float*)d_in[20];
    const float* m4_b3  = (const float*)d_in[21];
    float* out = (float*)d_out;

    cudaFuncSetAttribute(conv_mma_kernel,
                         cudaFuncAttributeMaxDynamicSharedMemorySize, CONV_SMEM);

    void *ph1, *plnh, *pt1, *pt2, *pt3, *pb3, *pb4;
    void *pw3a, *pw3b, *pw3c, *pw4a, *pw4b, *pw4c;
    cudaGetSymbolAddress(&ph1, g_h1);
    cudaGetSymbolAddress(&plnh, g_lnh);
    cudaGetSymbolAddress(&pt1, g_t1h);
    cudaGetSymbolAddress(&pt2, g_t2h);
    cudaGetSymbolAddress(&pt3, g_t3h);
    cudaGetSymbolAddress(&pb3, g_bias3);
    cudaGetSymbolAddress(&pb4, g_bias4);
    cudaGetSymbolAddress(&pw3a, g_w3a);
    cudaGetSymbolAddress(&pw3b, g_w3b);
    cudaGetSymbolAddress(&pw3c, g_w3c);
    cudaGetSymbolAddress(&pw4a, g_w4a);
    cudaGetSymbolAddress(&pw4b, g_w4b);
    cudaGetSymbolAddress(&pw4c, g_w4c);

    prep_w9h<<<1152, 256>>>(conv_w);
    prep_w1h<<<128, 256>>>(mlp1_w);
    prep_wh<<<32, 256>>>(m3_w1, (__half*)pw3a, 128, 64);
    prep_wh<<<16, 256>>>(m3_w2, (__half*)pw3b, 64, 64);
    prep_wh<<<32, 256>>>(m3_w3, (__half*)pw3c, 64, 128);
    prep_wh<<<32, 256>>>(m4_w1, (__half*)pw4a, 128, 64);
    prep_wh<<<16, 256>>>(m4_w2, (__half*)pw4b, 64, 64);
    prep_wh<<<32, 256>>>(m4_w3, (__half*)pw4c, 64, 128);
    prep_bias<<<1, 256>>>(s, mlp1_w, mlp1_b, m3_w1, m3_b1, m4_w1, m4_b1);

    upsample_fused_kernel<<<dim3(128, 8, 8), 256>>>(x);
    ycopy_kernel<<<dim3(8, 4, 2048), dim3(32, 8)>>>(y);
    conv_mma_kernel<<<4096, 128, CONV_SMEM>>>(conv_b);
    mlp1_mma_kernel<<<4096, 128>>>();

    // layernorm
    ln_part<<<dim3(512, 8), 256>>>();
    ln_finish<<<8, 256>>>();
    ln_apply<<<65536, 256>>>(ln_w, ln_b);

    // mlp3 (fp16)
    hgemm_kernel<128,64,0><<<4096, 128>>>((const __half*)plnh, (const __half*)pw3a,
                                          (const float*)pb3, (__half*)pt1, nullptr, nullptr);
    hgemm_kernel<64,64,1><<<4096, 128>>>((const __half*)pt1, (const __half*)pw3b,
                                         m3_b2, (__half*)pt2, nullptr, nullptr);
    hgemm_kernel<64,128,2><<<4096, 128>>>((const __half*)pt2, (const __half*)pw3c,
                                          m3_b3, (__half*)pt3, nullptr, nullptr);
    // mlp4 (+ identity add + NCHW scatter)
    hgemm_kernel<128,64,0><<<4096, 128>>>((const __half*)pt3, (const __half*)pw4a,
                                          (const float*)pb4, (__half*)pt1, nullptr, nullptr);
    hgemm_kernel<64,64,1><<<4096, 128>>>((const __half*)pt1, (const __half*)pw4b,
                                         m4_b2, (__half*)pt2, nullptr, nullptr);
    hgemm_kernel<64,128,3><<<4096, 128>>>((const __half*)pt2, (const __half*)pw4c,
                                          m4_b3, nullptr, out, (const float*)ph1);
}

// round 9
// speedup vs baseline: 4.2545x; 1.1024x over previous
#include <cuda_runtime.h>
#include <cuda_fp16.h>
#include <math.h>
#include <stdint.h>

#define BATCH 8
#define UPC   256
#define HH    256
#define WWD   256
#define HWN   65536
#define MTOT  (BATCH*HWN)   // 524288

// ---------------- scratch (static device globals; allocation-free) ----------------
__device__ __half g_xuPh[(size_t)BATCH*HWN*UPC];   // [b][h][c8][w][32] pair-interleaved half
__device__ __half g_fh  [(size_t)MTOT*256];        // concat(xc,y) NHWC, pair-interleaved half
__device__ float  g_h1 [(size_t)MTOT*128];         // mlp1 out fp32 (LN stats + identity)
__device__ __half g_lnh[(size_t)MTOT*128];         // layernorm out, interleaved half
__device__ __half g_t3h[(size_t)MTOT*128];         // collapsed-mlp3 out
__device__ __half g_w9ph[9*8*128*32];              // conv weights [off][c8][co][32] interleaved
__device__ __half g_w1h [128*256];                 // mlp1 W^T [n][k-interleaved]
__device__ __half g_w3comb[128*128];               // w3_1*w3_2*w3_3, [n][k-interleaved]
__device__ __half g_w4comb[128*128];
__device__ float  g_wtmp[128*64];                  // fp32 combine scratch
__device__ __half g_lnwh[(size_t)HWN*128];         // ln_w as half (natural order)
__device__ __half g_lnbh[(size_t)HWN*128];
__device__ float  g_bias1[BATCH*128];
__device__ float  g_bias3c[BATCH*128];
__device__ float  g_bias4c[BATCH*128];
__device__ float  g_part[BATCH*512*2];
__device__ float  g_stats[BATCH*2];

// channel c (0..31) -> half slot within 32-half chunk (pair-interleaved)
__device__ __forceinline__ int lam32(int c){
    int g  = c >> 4;
    int kp = (c & 15) >> 1;
    int o  = c & 1;
    return 8*(kp & 3) + 4*g + 2*(kp >> 2) + o;
}

__device__ __forceinline__ void mma_fp16(float c[4],
        uint32_t a0, uint32_t a1, uint32_t a2, uint32_t a3,
        uint32_t b0, uint32_t b1){
    asm volatile(
        "mma.sync.aligned.m16n8k16.row.col.f32.f16.f16.f32 "
        "{%0,%1,%2,%3}, {%4,%5,%6,%7}, {%8,%9}, {%0,%1,%2,%3};"
        : "+f"(c[0]), "+f"(c[1]), "+f"(c[2]), "+f"(c[3])
        : "r"(a0), "r"(a1), "r"(a2), "r"(a3), "r"(b0), "r"(b1));
}

__device__ __forceinline__ void cp16(uint32_t dst, const void* src, int bytes){
    asm volatile("cp.async.cg.shared.global [%0], [%1], 16, %2;"
                 :: "r"(dst), "l"(src), "r"(bytes));
}
__device__ __forceinline__ void cp_commit(){ asm volatile("cp.async.commit_group;"); }
__device__ __forceinline__ void cp_wait1(){ asm volatile("cp.async.wait_group 1;"); }
__device__ __forceinline__ void cp_wait0(){ asm volatile("cp.async.wait_group 0;"); }

// ---------------- prep kernels ----------------
__global__ void prep_w9h(const float* __restrict__ cw){
    int i = blockIdx.x*256 + threadIdx.x;
    if (i < 9*8*128*32){
        int c   = i & 31;
        int co  = (i >> 5) & 127;
        int c8  = (i >> 12) & 7;
        int off = i >> 15;
        int ci  = c8*32 + c;
        g_w9ph[(((off*8 + c8)*128 + co)*32) + lam32(c)] =
            __float2half_rn(cw[(co*256 + ci)*9 + off]);
    }
}

__global__ void prep_w1h(const float* __restrict__ w1){
    int i = blockIdx.x*256 + threadIdx.x;
    if (i < 128*256){
        int k = i & 255, n = i >> 8;
        g_w1h[n*256 + (k>>5)*32 + lam32(k & 31)] = __float2half_rn(w1[k*128 + n]);
    }
}

// tmp = w1[0:128] @ w2   (128x64 . 64x64)
__global__ void combine_w12(const float* __restrict__ w1, const float* __restrict__ w2){
    int i = blockIdx.x*256 + threadIdx.x;
    if (i < 8192){
        int k = i >> 6, j = i & 63;
        float s = 0.f;
        #pragma unroll 8
        for (int t = 0; t < 64; t++) s += w1[k*64 + t]*w2[t*64 + j];
        g_wtmp[k*64 + j] = s;
    }
}
// W = tmp @ w3 (128x64 . 64x128) -> half interleaved [n][k]
__global__ void combine_w3(const float* __restrict__ w3, __half* __restrict__ o){
    int i = blockIdx.x*256 + threadIdx.x;
    if (i < 16384){
        int k = i >> 7, n = i & 127;
        float s = 0.f;
        #pragma unroll 8
        for (int j = 0; j < 64; j++) s += g_wtmp[k*64 + j]*w3[j*128 + n];
        o[n*128 + (k>>5)*32 + lam32(k & 31)] = __float2half_rn(s);
    }
}
// combined per-batch bias: ((b1 + s*w1[128,:]) @ w2 + b2) @ w3 + b3
__global__ void combine_bias(const float* __restrict__ sv,
                             const float* __restrict__ w1, const float* __restrict__ b1,
                             const float* __restrict__ w2, const float* __restrict__ b2,
                             const float* __restrict__ w3, const float* __restrict__ b3,
                             float* __restrict__ ob){
    __shared__ float v[64], u[64];
    int t = threadIdx.x;
    for (int b = 0; b < BATCH; b++){
        float sb = sv[b];
        if (t < 64) v[t] = b1[t] + sb*w1[128*64 + t];
        __syncthreads();
        if (t < 64){
            float s = b2[t];
            #pragma unroll 8
            for (int i = 0; i < 64; i++) s += v[i]*w2[i*64 + t];
            u[t] = s;
        }
        __syncthreads();
        float s = b3[t];
        #pragma unroll 8
        for (int j = 0; j < 64; j++) s += u[j]*w3[j*128 + t];
        ob[b*128 + t] = s;
        __syncthreads();
    }
}

__global__ void prep_bias1(const float* __restrict__ s,
                           const float* __restrict__ m1w, const float* __restrict__ m1b){
    int t = threadIdx.x;
    if (t < 128)
        for (int b = 0; b < BATCH; b++)
            g_bias1[b*128+t] = m1b[t] + s[b]*m1w[256*128 + t];
}

__global__ void prep_lnh(const float* __restrict__ lnw, const float* __restrict__ lnb){
    size_t e = ((size_t)blockIdx.x*256 + threadIdx.x)*4;   // 8388608 elems, 4 each
    float4 w = *(const float4*)&lnw[e];
    float4 b = *(const float4*)&lnb[e];
    *(__half2*)(g_lnwh + e)     = __floats2half2_rn(w.x, w.y);
    *(__half2*)(g_lnwh + e + 2) = __floats2half2_rn(w.z, w.w);
    *(__half2*)(g_lnbh + e)     = __floats2half2_rn(b.x, b.y);
    *(__half2*)(g_lnbh + e + 2) = __floats2half2_rn(b.z, b.w);
}

// ---------------- fused bicubic 2x upsample -> interleaved half (g_xuPh) ----------------
__global__ __launch_bounds__(256) void upsample_fused_kernel(const float* __restrict__ x){
    __shared__ __half sm[2][256][32];
    int kh = blockIdx.x, c8 = blockIdx.y, b = blockIdx.z;
    int tid = threadIdx.x;
    int lane = tid & 31, warp = tid >> 5;

    int rr[5];
    #pragma unroll
    for (int i = 0; i < 5; i++){
        int r = kh - 2 + i; rr[i] = min(max(r,0),127);
    }
    const float we0=-0.03515625f, we1=0.26171875f, we2=0.87890625f, we3=-0.10546875f;
    const float wo0=-0.10546875f, wo1=0.87890625f, wo2=0.26171875f, wo3=-0.03515625f;

    #pragma unroll
    for (int q = 0; q < 4; q++){
        int cg = warp*4 + q;
        int c  = c8*32 + cg;
        const float* xp = x + ((size_t)(b*256 + c))*16384;
        int slot = lam32(cg);
        #pragma unroll
        for (int j = 0; j < 4; j++){
            int kw = lane + 32*j;
            int cc[5];
            #pragma unroll
            for (int i = 0; i < 5; i++){
                int cw_ = kw - 2 + i; cc[i] = min(max(cw_,0),127);
            }
            float he[5], ho[5];
            #pragma unroll
            for (int i = 0; i < 5; i++){
                const float* row = xp + rr[i]*128;
                float v0=row[cc[0]], v1=row[cc[1]], v2=row[cc[2]], v3=row[cc[3]], v4=row[cc[4]];
                he[i] = we0*v0 + we1*v1 + we2*v2 + we3*v3;
                ho[i] = wo0*v1 + wo1*v2 + wo2*v3 + wo3*v4;
            }
            float o00 = we0*he[0]+we1*he[1]+we2*he[2]+we3*he[3];
            float o01 = we0*ho[0]+we1*ho[1]+we2*ho[2]+we3*ho[3];
            float o10 = wo0*he[1]+wo1*he[2]+wo2*he[3]+wo3*he[4];
            float o11 = wo0*ho[1]+wo1*ho[2]+wo2*ho[3]+wo3*ho[4];
            sm[0][2*kw  ][slot] = __float2half_rn(o00);
            sm[0][2*kw+1][slot] = __float2half_rn(o01);
            sm[1][2*kw  ][slot] = __float2half_rn(o10);
            sm[1][2*kw+1][slot] = __float2half_rn(o11);
        }
    }
    __syncthreads();

    __half* out0 = g_xuPh + ((size_t)((b*256 + 2*kh    )*8 + c8))*8192;
    __half* out1 = g_xuPh + ((size_t)((b*256 + 2*kh + 1)*8 + c8))*8192;
    const uint4* s0 = (const uint4*)&sm[0][0][0];
    const uint4* s1 = (const uint4*)&sm[1][0][0];
    #pragma unroll
    for (int p = 0; p < 4; p++){
        ((uint4*)out0)[p*256 + tid] = s0[p*256 + tid];
        ((uint4*)out1)[p*256 + tid] = s1[p*256 + tid];
    }
}

// ---------------- y NCHW -> f half (channels 128..255, interleaved slots) ----------------
__global__ void ycopy_kernel(const float* __restrict__ y){
    __shared__ float tile[32][33];
    int w0 = blockIdx.x*32, cb = blockIdx.y;
    int bh = blockIdx.z;
    int b = bh >> 8, h = bh & 255;
    int tx = threadIdx.x, ty = threadIdx.y;
    int c0 = cb*32;
    #pragma unroll
    for (int k = 0; k < 4; k++){
        int c = c0 + ty + k*8;
        tile[ty + k*8][tx] = y[(((size_t)b*128 + c)*256 + h)*256 + w0 + tx];
    }
    __syncthreads();
    int slot = (4 + cb)*32 + lam32(tx);
    #pragma unroll
    for (int k = 0; k < 4; k++){
        int w = w0 + ty + k*8;
        g_fh[(((size_t)b*256 + h)*256 + w)*256 + slot] = __float2half_rn(tile[tx][ty + k*8]);
    }
}

// ---------------- conv 3x3 via fp16 mma, cp.async double-buffered ----------------
#define CONV_SMEM 65792

__global__ __launch_bounds__(128, 2) void conv_mma_kernel(const float* __restrict__ convb){
    extern __shared__ char dsm[];
    char* const Ab[2] = {dsm, dsm + 8320};
    char* const Bb[2] = {dsm + 16640, dsm + 41216};
    uint32_t Au[2], Bu[2];
    Au[0] = (uint32_t)__cvta_generic_to_shared(Ab[0]);
    Au[1] = (uint32_t)__cvta_generic_to_shared(Ab[1]);
    Bu[0] = (uint32_t)__cvta_generic_to_shared(Bb[0]);
    Bu[1] = (uint32_t)__cvta_generic_to_shared(Bb[1]);

    int bx = blockIdx.x;
    int w0 = (bx & 1)*128;
    int h  = (bx >> 1) & 255;
    int b  = bx >> 9;
    int tid = threadIdx.x;
    int wid = tid >> 5, lane = tid & 31;
    int wm = wid & 1, wn = wid >> 1;
    int lr = lane >> 2, lc = lane & 3;

    int hhs[3], off3s[3], nh = 0;
    #pragma unroll
    for (int dh = -1; dh <= 1; dh++){
        int hh = h + dh;
        if (hh >= 0 && hh < HH){ hhs[nh] = hh; off3s[nh] = (dh+1)*3; nh++; }
    }
    int nch = nh*8;

    float acc[4][8][4];
    #pragma unroll
    for (int mi = 0; mi < 4; mi++)
        #pragma unroll
        for (int ni = 0; ni < 8; ni++)
            #pragma unroll
            for (int r = 0; r < 4; r++) acc[mi][ni][r] = 0.f;

    auto fill = [&](int i, int s){
        int ih = i >> 3, c8 = i & 7;
        const __half* aplane = g_xuPh + ((size_t)((b*256 + hhs[ih])*8 + c8))*8192;
        #pragma unroll
        for (int p = 0; p < 5; p++){
            int idx = tid + p*128;
            if (idx < 520){
                int row = idx >> 2, t = idx & 3;
                int w_in = w0 - 1 + row;
                int ok = (w_in >= 0 && w_in < WWD) ? 16 : 0;
                int wc = min(max(w_in, 0), WWD-1);
                cp16(Au[s] + row*64 + (16*t ^ ((row & 1) << 5)),
                     aplane + wc*32 + t*8, ok);
            }
        }
        const __half* wb = g_w9ph + ((size_t)(off3s[ih]*8 + c8))*128*32;
        #pragma unroll
        for (int p = 0; p < 12; p++){
            int idx = tid + p*128;
            int row = idx >> 2, t = idx & 3;
            int dwi = row >> 7, co = row & 127;
            cp16(Bu[s] + row*64 + (16*t ^ ((row & 1) << 5)),
                 wb + ((size_t)dwi*8*128*32) + co*32 + t*8, 16);
        }
    };

    fill(0, 0);
    cp_commit();

    for (int i = 0; i < nch; i++){
        int s = i & 1;
        if (i + 1 < nch){ fill(i+1, s^1); cp_commit(); cp_wait1(); }
        else cp_wait0();
        __syncthreads();

        char* As = Ab[s];
        char* Bs = Bb[s];
        #pragma unroll
        for (int dwi = 0; dwi < 3; dwi++){
            uint4 bf[8];
            #pragma unroll
            for (int ni = 0; ni < 8; ni++){
                int brow = dwi*128 + wn*64 + ni*8 + lr;
                bf[ni] = *(const uint4*)(Bs + brow*64 + (16*lc ^ ((brow & 1) << 5)));
            }
            #pragma unroll
            for (int mi = 0; mi < 4; mi++){
                int ar0 = wm*64 + mi*16 + lr + dwi;
                int ar1 = ar0 + 8;
                uint4 A1 = *(const uint4*)(As + ar0*64 + (16*lc ^ ((ar0 & 1) << 5)));
                uint4 A2 = *(const uint4*)(As + ar1*64 + (16*lc ^ ((ar1 & 1) << 5)));
                #pragma unroll
                for (int ni = 0; ni < 8; ni++){
                    mma_fp16(acc[mi][ni], A1.x, A2.x, A1.y, A2.y, bf[ni].x, bf[ni].y);
                    mma_fp16(acc[mi][ni], A1.z, A2.z, A1.w, A2.w, bf[ni].z, bf[ni].w);
                }
            }
        }
        __syncthreads();
    }

    float bv0[8], bv1[8];
    int slot[8];
    #pragma unroll
    for (int ni = 0; ni < 8; ni++){
        int n = wn*64 + ni*8 + lc*2;
        bv0[ni] = convb[n];
        bv1[ni] = convb[n+1];
        slot[ni] = (n >> 5)*32 + lam32(n & 31);
    }
    #pragma unroll
    for (int mi = 0; mi < 4; mi++){
        int m0 = wm*64 + mi*16 + lr;
        __half* dst0 = g_fh + (((size_t)b*256 + h)*256 + w0 + m0    )*256;
        __half* dst1 = g_fh + (((size_t)b*256 + h)*256 + w0 + m0 + 8)*256;
        #pragma unroll
        for (int ni = 0; ni < 8; ni++){
            *(__half2*)(dst0 + slot[ni]) =
                __floats2half2_rn(acc[mi][ni][0] + bv0[ni], acc[mi][ni][1] + bv1[ni]);
            *(__half2*)(dst1 + slot[ni]) =
                __floats2half2_rn(acc[mi][ni][2] + bv0[ni], acc[mi][ni][3] + bv1[ni]);
        }
    }
}

// ---------------- mlp1 via fp16 mma + fused LN partial sums ----------------
__global__ __launch_bounds__(128, 2) void mlp1_mma_kernel(){
    __shared__ __align__(16) char As[2][8192];
    __shared__ __align__(16) char Bs[2][8192];
    __shared__ float shs[128], shs2[128];
    uint32_t AsU[2], BsU[2];
    AsU[0] = (uint32_t)__cvta_generic_to_shared(As[0]);
    AsU[1] = (uint32_t)__cvta_generic_to_shared(As[1]);
    BsU[0] = (uint32_t)__cvta_generic_to_shared(Bs[0]);
    BsU[1] = (uint32_t)__cvta_generic_to_shared(Bs[1]);

    int m0  = blockIdx.x*128;
    int tid = threadIdx.x;
    int wid = tid >> 5, lane = tid & 31;
    int wm = wid & 1, wn = wid >> 1;
    int lr = lane >> 2, lc = lane & 3;

    float acc[4][8][4];
    #pragma unroll
    for (int mi = 0; mi < 4; mi++)
        #pragma unroll
        for (int ni = 0; ni < 8; ni++)
            #pragma unroll
            for (int r = 0; r < 4; r++) acc[mi][ni][r] = 0.f;

    auto fill = [&](int chunk, int s){
        #pragma unroll
        for (int p = 0; p < 4; p++){
            int idx = tid + p*128;
            int row = idx >> 2, t = idx & 3;
            uint32_t sw = 16*t ^ ((row & 1) << 5);
            cp16(AsU[s] + row*64 + sw,
                 g_fh + ((size_t)(m0 + row)*256 + chunk*32) + t*8, 16);
            cp16(BsU[s] + row*64 + sw,
                 g_w1h + (row*256 + chunk*32) + t*8, 16);
        }
    };

    fill(0, 0);
    cp_commit();

    for (int chunk = 0; chunk < 8; chunk++){
        int s = chunk & 1;
        if (chunk + 1 < 8){ fill(chunk+1, s^1); cp_commit(); cp_wait1(); }
        else cp_wait0();
        __syncthreads();

        uint4 bf[8];
        #pragma unroll
        for (int ni = 0; ni < 8; ni++){
            int brow = wn*64 + ni*8 + lr;
            bf[ni] = *(const uint4*)(Bs[s] + brow*64 + (16*lc ^ ((brow & 1) << 5)));
        }
        #pragma unroll
        for (int mi = 0; mi < 4; mi++){
            int ar0 = wm*64 + mi*16 + lr;
            int ar1 = ar0 + 8;
            uint4 A1 = *(const uint4*)(As[s] + ar0*64 + (16*lc ^ ((ar0 & 1) << 5)));
            uint4 A2 = *(const uint4*)(As[s] + ar1*64 + (16*lc ^ ((ar1 & 1) << 5)));
            #pragma unroll
            for (int ni = 0; ni < 8; ni++){
                mma_fp16(acc[mi][ni], A1.x, A2.x, A1.y, A2.y, bf[ni].x, bf[ni].y);
                mma_fp16(acc[mi][ni], A1.z, A2.z, A1.w, A2.w, bf[ni].z, bf[ni].w);
            }
        }
        __syncthreads();
    }

    int b = m0 >> 16;
    float bv0[8], bv1[8];
    #pragma unroll
    for (int ni = 0; ni < 8; ni++){
        int n = wn*64 + ni*8 + lc*2;
        bv0[ni] = g_bias1[b*128 + n];
        bv1[ni] = g_bias1[b*128 + n + 1];
    }
    float ts = 0.f, ts2 = 0.f;
    #pragma unroll
    for (int mi = 0; mi < 4; mi++){
        int mr = m0 + wm*64 + mi*16 + lr;
        float* dst0 = g_h1 + (size_t)mr*128;
        float* dst1 = g_h1 + (size_t)(mr + 8)*128;
        #pragma unroll
        for (int ni = 0; ni < 8; ni++){
            int n = wn*64 + ni*8 + lc*2;
            float v0 = fmaxf(acc[mi][ni][0] + bv0[ni], 0.f);
            float v1 = fmaxf(acc[mi][ni][1] + bv1[ni], 0.f);
            float v2 = fmaxf(acc[mi][ni][2] + bv0[ni], 0.f);
            float v3 = fmaxf(acc[mi][ni][3] + bv1[ni], 0.f);
            *(float2*)(dst0 + n) = make_float2(v0, v1);
            *(float2*)(dst1 + n) = make_float2(v2, v3);
            ts  += v0 + v1 + v2 + v3;
            ts2 += v0*v0 + v1*v1 + v2*v2 + v3*v3;
        }
    }
    // deterministic CTA reduction -> g_part
    shs[tid] = ts; shs2[tid] = ts2;
    __syncthreads();
    for (int st = 64; st > 0; st >>= 1){
        if (tid < st){ shs[tid] += shs[tid+st]; shs2[tid] += shs2[tid+st]; }
        __syncthreads();
    }
    if (tid == 0){
        int cta = blockIdx.x & 511;
        g_part[(b*512 + cta)*2    ] = shs[0];
        g_part[(b*512 + cta)*2 + 1] = shs2[0];
    }
}

// ---------------- collapsed-chain fp16 GEMM: K=128, N=128 ----------------
// EPI 0: per-batch bias + relu -> half interleaved
// EPI 1: per-batch bias + relu + identity(fp32) + NCHW scatter -> fp32
template<int EPI>
__global__ __launch_bounds__(128, 2) void hgemm2_kernel(
    const __half* __restrict__ A, const __half* __restrict__ Bw,
    const float* __restrict__ biasPB,
    __half* __restrict__ outh, float* __restrict__ outf,
    const float* __restrict__ identity)
{
    __shared__ __align__(16) char As[128*64];
    __shared__ __align__(16) char Bs[128*64];

    int m0  = blockIdx.x*128;
    int tid = threadIdx.x;
    int wid = tid >> 5, lane = tid & 31;
    int wm = wid & 1, wn = wid >> 1;
    int lr = lane >> 2, lc = lane & 3;

    float acc[4][8][4];
    #pragma unroll
    for (int mi = 0; mi < 4; mi++)
        #pragma unroll
        for (int ni = 0; ni < 8; ni++)
            #pragma unroll
            for (int r = 0; r < 4; r++) acc[mi][ni][r] = 0.f;

    #pragma unroll
    for (int chunk = 0; chunk < 4; chunk++){
        if (chunk) __syncthreads();
        #pragma unroll
        for (int p = 0; p < 4; p++){
            int idx = tid + p*128;
            int row = idx >> 2, t = idx & 3;
            uint32_t sw = 16*t ^ ((row & 1) << 5);
            uint4 va = *(const uint4*)(A + ((size_t)(m0 + row)*128 + chunk*32) + t*8);
            *(uint4*)(As + row*64 + sw) = va;
            uint4 vb = *(const uint4*)(Bw + ((size_t)row*128 + chunk*32) + t*8);
            *(uint4*)(Bs + row*64 + sw) = vb;
        }
        __syncthreads();

        uint4 bf[8];
        #pragma unroll
        for (int ni = 0; ni < 8; ni++){
            int brow = wn*64 + ni*8 + lr;
            bf[ni] = *(const uint4*)(Bs + brow*64 + (16*lc ^ ((brow & 1) << 5)));
        }
        #pragma unroll
        for (int mi = 0; mi < 4; mi++){
            int ar0 = wm*64 + mi*16 + lr;
            int ar1 = ar0 + 8;
            uint4 A1 = *(const uint4*)(As + ar0*64 + (16*lc ^ ((ar0 & 1) << 5)));
            uint4 A2 = *(const uint4*)(As + ar1*64 + (16*lc ^ ((ar1 & 1) << 5)));
            #pragma unroll
            for (int ni = 0; ni < 8; ni++){
                mma_fp16(acc[mi][ni], A1.x, A2.x, A1.y, A2.y, bf[ni].x, bf[ni].y);
                mma_fp16(acc[mi][ni], A1.z, A2.z, A1.w, A2.w, bf[ni].z, bf[ni].w);
            }
        }
    }

    int b = m0 >> 16;
    const float* bp = biasPB + b*128;
    float bv0[8], bv1[8];
    int slot[8];
    #pragma unroll
    for (int ni = 0; ni < 8; ni++){
        int n = wn*64 + ni*8 + lc*2;
        bv0[ni] = bp[n];
        bv1[ni] = bp[n+1];
        slot[ni] = (n >> 5)*32 + lam32(n & 31);
    }

    #pragma unroll
    for (int mi = 0; mi < 4; mi++){
        int mr = m0 + wm*64 + mi*16 + lr;
        if constexpr (EPI == 1){
            int hw0 = mr & 65535, hw1 = (mr + 8) & 65535;
            const float* id0 = identity + (size_t)mr*128;
            const float* id1 = identity + (size_t)(mr + 8)*128;
            #pragma unroll
            for (int ni = 0; ni < 8; ni++){
                int n = wn*64 + ni*8 + lc*2;
                float* o0 = outf + ((size_t)(b*128 + n))*65536;
                float* o1 = outf + ((size_t)(b*128 + n + 1))*65536;
                o0[hw0] = fmaxf(acc[mi][ni][0] + bv0[ni], 0.f) + id0[n];
                o1[hw0] = fmaxf(acc[mi][ni][1] + bv1[ni], 0.f) + id0[n+1];
                o0[hw1] = fmaxf(acc[mi][ni][2] + bv0[ni], 0.f) + id1[n];
                o1[hw1] = fmaxf(acc[mi][ni][3] + bv1[ni], 0.f) + id1[n+1];
            }
        } else {
            __half* dst0 = outh + (size_t)mr*128;
            __half* dst1 = outh + (size_t)(mr + 8)*128;
            #pragma unroll
            for (int ni = 0; ni < 8; ni++){
                *(__half2*)(dst0 + slot[ni]) =
                    __floats2half2_rn(fmaxf(acc[mi][ni][0] + bv0[ni], 0.f),
                                      fmaxf(acc[mi][ni][1] + bv1[ni], 0.f));
                *(__half2*)(dst1 + slot[ni]) =
                    __floats2half2_rn(fmaxf(acc[mi][ni][2] + bv0[ni], 0.f),
                                      fmaxf(acc[mi][ni][3] + bv1[ni], 0.f));
            }
        }
    }
}

// ---------------- layernorm finish + apply ----------------
__global__ void ln_finish(){
    int b = blockIdx.x, tid = threadIdx.x;
    float s = 0.f, s2 = 0.f;
    for (int i = tid; i < 512; i += 256){
        s  += g_part[(b*512 + i)*2];
        s2 += g_part[(b*512 + i)*2 + 1];
    }
    __shared__ float sh[256], sh2[256];
    sh[tid] = s; sh2[tid] = s2; __syncthreads();
    for (int st = 128; st > 0; st >>= 1){
        if (tid < st){ sh[tid] += sh[tid+st]; sh2[tid] += sh2[tid+st]; }
        __syncthreads();
    }
    if (tid == 0){
        const float invN = 1.f / 8388608.f;
        float mu  = sh[0] * invN;
        float var = sh2[0] * invN - mu*mu;
        g_stats[b*2]     = mu;
        g_stats[b*2 + 1] = rsqrtf(var + 1e-5f);
    }
}

__global__ void ln_apply(){
    size_t e = ((size_t)blockIdx.x*256 + threadIdx.x)*4;
    int b = (int)(e >> 23);
    float mu = g_stats[b*2], rs = g_stats[b*2 + 1];
    size_t li = e & 8388607u;
    int m = (int)(e >> 7);
    int c = (int)(e & 127);
    float4 h = *(const float4*)&g_h1[e];
    __half2 w01 = *(const __half2*)(g_lnwh + li);
    __half2 w23 = *(const __half2*)(g_lnwh + li + 2);
    __half2 b01 = *(const __half2*)(g_lnbh + li);
    __half2 b23 = *(const __half2*)(g_lnbh + li + 2);
    float2 wf0 = __half22float2(w01), wf1 = __half22float2(w23);
    float2 bf0 = __half22float2(b01), bf1 = __half22float2(b23);
    float o0 = (h.x - mu)*rs*wf0.x + bf0.x;
    float o1 = (h.y - mu)*rs*wf0.y + bf0.y;
    float o2 = (h.z - mu)*rs*wf1.x + bf1.x;
    float o3 = (h.w - mu)*rs*wf1.y + bf1.y;
    __half* dst = g_lnh + (size_t)m*128;
    int s0 = (c >> 5)*32 + lam32(c & 31);
    int s1 = ((c+2) >> 5)*32 + lam32((c+2) & 31);
    *(__half2*)(dst + s0) = __floats2half2_rn(o0, o1);
    *(__half2*)(dst + s1) = __floats2half2_rn(o2, o3);
}

// ---------------- launch ----------------
extern "C" void kernel_launch(void* const* d_in, const int* in_sizes, int n_in,
                              void* d_out, int out_size){
    const float* x      = (const float*)d_in[0];
    const float* y      = (const float*)d_in[1];
    const float* s      = (const float*)d_in[2];
    const float* conv_w = (const float*)d_in[4];
    const float* conv_b = (const float*)d_in[5];
    const float* mlp1_w = (const float*)d_in[6];
    const float* mlp1_b = (const float*)d_in[7];
    const float* ln_w   = (const float*)d_in[8];
    const float* ln_b   = (const float*)d_in[9];
    const float* m3_w1  = (const float*)d_in[10];
    const float* m3_b1  = (const float*)d_in[11];
    const float* m3_w2  = (const float*)d_in[12];
    const float* m3_b2  = (const float*)d_in[13];
    const float* m3_w3  = (const float*)d_in[14];
    const float* m3_b3  = (const float*)d_in[15];
    const float* m4_w1  = (const float*)d_in[16];
    const float* m4_b1  = (const float*)d_in[17];
    const float* m4_w2  = (const float*)d_in[18];
    const float* m4_b2  = (const float*)d_in[19];
    const float* m4_w3  = (const float*)d_in[20];
    const float* m4_b3  = (const float*)d_in[21];
    float* out = (float*)d_out;

    cudaFuncSetAttribute(conv_mma_kernel,
                         cudaFuncAttributeMaxDynamicSharedMemorySize, CONV_SMEM);

    void *ph1, *plnh, *pt3, *pw3c, *pw4c, *pb3c, *pb4c;
    cudaGetSymbolAddress(&ph1, g_h1);
    cudaGetSymbolAddress(&plnh, g_lnh);
    cudaGetSymbolAddress(&pt3, g_t3h);
    cudaGetSymbolAddress(&pw3c, g_w3comb);
    cudaGetSymbolAddress(&pw4c, g_w4comb);
    cudaGetSymbolAddress(&pb3c, g_bias3c);
    cudaGetSymbolAddress(&pb4c, g_bias4c);

    // weight prep (combined chain weights; sequential stream order gives deps)
    prep_w9h<<<1152, 256>>>(conv_w);
    prep_w1h<<<128, 256>>>(mlp1_w);
    combine_w12<<<32, 256>>>(m3_w1, m3_w2);
    combine_w3<<<64, 256>>>(m3_w3, (__half*)pw3c);
    combine_w12<<<32, 256>>>(m4_w1, m4_w2);
    combine_w3<<<64, 256>>>(m4_w3, (__half*)pw4c);
    combine_bias<<<1, 128>>>(s, m3_w1, m3_b1, m3_w2, m3_b2, m3_w3, m3_b3, (float*)pb3c);
    combine_bias<<<1, 128>>>(s, m4_w1, m4_b1, m4_w2, m4_b2, m4_w3, m4_b3, (float*)pb4c);
    prep_bias1<<<1, 128>>>(s, mlp1_w, mlp1_b);
    prep_lnh<<<8192, 256>>>(ln_w, ln_b);

    upsample_fused_kernel<<<dim3(128, 8, 8), 256>>>(x);
    ycopy_kernel<<<dim3(8, 4, 2048), dim3(32, 8)>>>(y);
    conv_mma_kernel<<<4096, 128, CONV_SMEM>>>(conv_b);
    mlp1_mma_kernel<<<4096, 128>>>();        // writes h1 + LN partials

    ln_finish<<<8, 256>>>();
    ln_apply<<<65536, 256>>>();

    // collapsed chains
    hgemm2_kernel<0><<<4096, 128>>>((const __half*)plnh, (const __half*)pw3c,
                                    (const float*)pb3c, (__half*)pt3, nullptr, nullptr);
    hgemm2_kernel<1><<<4096, 128>>>((const __half*)pt3, (const __half*)pw4c,
                                    (const float*)pb4c, nullptr, out, (const float*)ph1);
}